// round 1
// baseline (speedup 1.0000x reference)
#include <cuda_runtime.h>
#include <cuda_bf16.h>
#include <math.h>

#define B_  2
#define L_  2048
#define C_  1024
#define H_  16
#define HD_ 64
#define FF_ 4096
#define ROWS (B_*L_)          // 4096
#define SCALE_ 0.125f         // 64^-0.5
#define EPS_ 1e-5f

// ---------------- scratch (allocation-free rule: __device__ globals) --------
__device__ float g_xn  [ROWS*C_];        // LN1 out
__device__ float g_qkv [ROWS*3*C_];      // qkv proj out
__device__ float g_fbg [ROWS*C_];        // gelu(ln(freq outer)) out
__device__ float g_fb2 [ROWS*C_];        // fb @ fp_w2
__device__ float g_Qe  [B_*H_*L_*128];   // [SCALE*q , fs*qb]
__device__ float g_Ke  [B_*H_*L_*128];   // [k , kb]
__device__ float g_V   [B_*H_*L_*HD_];
__device__ float g_O   [ROWS*C_];        // attention out [B,L,C]
__device__ float g_xmid[ROWS*C_];        // after attn residual
__device__ float g_xn2 [ROWS*C_];        // LN2 out
__device__ float g_h   [ROWS*FF_];       // mlp hidden

__device__ __forceinline__ float gelu_exact(float v) {
    return 0.5f * v * (1.0f + erff(v * 0.70710678118654752f));
}

// ---------------- LayerNorm: one block per row (C=1024) ---------------------
__global__ void ln_kernel(const float* __restrict__ X, const float* __restrict__ g,
                          const float* __restrict__ b, float* __restrict__ Y) {
    int row = blockIdx.x;
    int tid = threadIdx.x;                       // 256 threads, 1 float4 each
    const float4* xr = (const float4*)(X + (size_t)row * C_);
    float4 t = xr[tid];
    float s  = t.x + t.y + t.z + t.w;
    float sq = t.x*t.x + t.y*t.y + t.z*t.z + t.w*t.w;
    #pragma unroll
    for (int o = 16; o; o >>= 1) {
        s  += __shfl_xor_sync(0xffffffffu, s,  o);
        sq += __shfl_xor_sync(0xffffffffu, sq, o);
    }
    __shared__ float ws[8], wq[8];
    __shared__ float mean_s, rstd_s;
    int w = tid >> 5;
    if ((tid & 31) == 0) { ws[w] = s; wq[w] = sq; }
    __syncthreads();
    if (tid == 0) {
        float S = 0.f, Q = 0.f;
        #pragma unroll
        for (int i = 0; i < 8; i++) { S += ws[i]; Q += wq[i]; }
        float mean = S * (1.0f / C_);
        float var  = Q * (1.0f / C_) - mean * mean;
        mean_s = mean; rstd_s = rsqrtf(var + EPS_);
    }
    __syncthreads();
    float mean = mean_s, rstd = rstd_s;
    float4 gg = ((const float4*)g)[tid];
    float4 bb = ((const float4*)b)[tid];
    float4 o;
    o.x = (t.x - mean) * rstd * gg.x + bb.x;
    o.y = (t.y - mean) * rstd * gg.y + bb.y;
    o.z = (t.z - mean) * rstd * gg.z + bb.z;
    o.w = (t.w - mean) * rstd * gg.w + bb.w;
    ((float4*)(Y + (size_t)row * C_))[tid] = o;
}

// ------------- freq path stage 1: rank-1 outer + LN + exact GELU ------------
__global__ void fb1_kernel(const float* __restrict__ fd, const float* __restrict__ w1,
                           const float* __restrict__ b1, const float* __restrict__ g,
                           const float* __restrict__ bln, float* __restrict__ Y) {
    int row = blockIdx.x;
    int tid = threadIdx.x;
    float f = fd[row];
    float4 w = ((const float4*)w1)[tid];
    float4 bb = ((const float4*)b1)[tid];
    float4 t;
    t.x = f * w.x + bb.x; t.y = f * w.y + bb.y;
    t.z = f * w.z + bb.z; t.w = f * w.w + bb.w;
    float s  = t.x + t.y + t.z + t.w;
    float sq = t.x*t.x + t.y*t.y + t.z*t.z + t.w*t.w;
    #pragma unroll
    for (int o = 16; o; o >>= 1) {
        s  += __shfl_xor_sync(0xffffffffu, s,  o);
        sq += __shfl_xor_sync(0xffffffffu, sq, o);
    }
    __shared__ float ws[8], wqs[8];
    __shared__ float mean_s, rstd_s;
    int w5 = tid >> 5;
    if ((tid & 31) == 0) { ws[w5] = s; wqs[w5] = sq; }
    __syncthreads();
    if (tid == 0) {
        float S = 0.f, Q = 0.f;
        #pragma unroll
        for (int i = 0; i < 8; i++) { S += ws[i]; Q += wqs[i]; }
        float mean = S * (1.0f / C_);
        float var  = Q * (1.0f / C_) - mean * mean;
        mean_s = mean; rstd_s = rsqrtf(var + EPS_);
    }
    __syncthreads();
    float mean = mean_s, rstd = rstd_s;
    float4 gg = ((const float4*)g)[tid];
    float4 bl = ((const float4*)bln)[tid];
    float4 o;
    o.x = gelu_exact((t.x - mean) * rstd * gg.x + bl.x);
    o.y = gelu_exact((t.y - mean) * rstd * gg.y + bl.y);
    o.z = gelu_exact((t.z - mean) * rstd * gg.z + bl.z);
    o.w = gelu_exact((t.w - mean) * rstd * gg.w + bl.w);
    ((float4*)(Y + (size_t)row * C_))[tid] = o;
}

// ---------------- SGEMM: C = act(A@B + bias) (+R). 128x128x16 tiles ---------
// A [M,K] rm, B [K,N] rm. M%128==0, N%128==0, K%16==0.  act: 0 none, 1 gelu.
__global__ __launch_bounds__(256) void gemm_kernel(
    const float* __restrict__ A, const float* __restrict__ Bm,
    const float* __restrict__ bias, const float* __restrict__ R,
    float* __restrict__ C, int M, int N, int K, int act) {
    __shared__ float As[16 * 128];   // transposed: As[k][m]
    __shared__ float Bs[16 * 128];   // Bs[k][n]
    int tid = threadIdx.x;
    int tx = tid & 15, ty = tid >> 4;
    int m0 = blockIdx.y * 128, n0 = blockIdx.x * 128;
    float acc[8][8];
    #pragma unroll
    for (int i = 0; i < 8; i++)
        #pragma unroll
        for (int j = 0; j < 8; j++) acc[i][j] = 0.f;

    for (int k0 = 0; k0 < K; k0 += 16) {
        #pragma unroll
        for (int it = 0; it < 2; it++) {
            int i = tid + it * 256;
            int row = i >> 2, kc = (i & 3) * 4;
            float4 v = *(const float4*)(A + (size_t)(m0 + row) * K + k0 + kc);
            As[(kc + 0) * 128 + row] = v.x;
            As[(kc + 1) * 128 + row] = v.y;
            As[(kc + 2) * 128 + row] = v.z;
            As[(kc + 3) * 128 + row] = v.w;
            int kr = i >> 5, c = (i & 31) * 4;
            float4 wv = *(const float4*)(Bm + (size_t)(k0 + kr) * N + n0 + c);
            *(float4*)(Bs + kr * 128 + c) = wv;
        }
        __syncthreads();
        #pragma unroll
        for (int k = 0; k < 16; k++) {
            float a[8], b[8];
            #pragma unroll
            for (int i = 0; i < 8; i++) a[i] = As[k * 128 + ty + 16 * i];
            #pragma unroll
            for (int j = 0; j < 8; j++) b[j] = Bs[k * 128 + tx + 16 * j];
            #pragma unroll
            for (int i = 0; i < 8; i++)
                #pragma unroll
                for (int j = 0; j < 8; j++) acc[i][j] += a[i] * b[j];
        }
        __syncthreads();
    }
    #pragma unroll
    for (int i = 0; i < 8; i++) {
        int row = m0 + ty + 16 * i;
        #pragma unroll
        for (int j = 0; j < 8; j++) {
            int col = n0 + tx + 16 * j;
            float v = acc[i][j] + bias[col];
            if (act == 1) v = gelu_exact(v);
            if (R) v += R[(size_t)row * N + col];
            C[(size_t)row * N + col] = v;
        }
    }
}

// ------- build extended Q/K and V: fold freq bias into extra 64 dims --------
__global__ void build_ext_kernel(const float* __restrict__ qkv, const float* __restrict__ fb2,
                                 const float* __restrict__ wqw, const float* __restrict__ wqb,
                                 const float* __restrict__ wkw, const float* __restrict__ wkb,
                                 const float* __restrict__ fscale,
                                 float* __restrict__ Qe, float* __restrict__ Ke,
                                 float* __restrict__ Vo) {
    __shared__ float swq[64 * 64], swk[64 * 64], sfb[64 * 65];
    int bh = blockIdx.y;               // b*16+h
    int lt = blockIdx.x;               // 64-row tile of L
    int b = bh >> 4, h = bh & 15;
    int l0 = lt * 64;
    int tid = threadIdx.x;             // 256
    for (int i = tid; i < 4096; i += 256) { swq[i] = wqw[i]; swk[i] = wkw[i]; }
    for (int i = tid; i < 4096; i += 256) {
        int r = i >> 6, c = i & 63;
        sfb[r * 65 + c] = fb2[(size_t)(b * L_ + l0 + r) * C_ + h * 64 + c];
    }
    __syncthreads();
    int r = tid >> 2, q4 = tid & 3;
    float fs = fscale[0];
    float aq[16], ak[16];
    #pragma unroll
    for (int d = 0; d < 16; d++) { aq[d] = wqb[q4 * 16 + d]; ak[d] = wkb[q4 * 16 + d]; }
    for (int e = 0; e < 64; e++) {
        float fe = sfb[r * 65 + e];
        #pragma unroll
        for (int d = 0; d < 16; d++) {
            aq[d] += fe * swq[e * 64 + q4 * 16 + d];
            ak[d] += fe * swk[e * 64 + q4 * 16 + d];
        }
    }
    size_t base = (size_t)bh * L_ + l0 + r;
    float* qrow = Qe + base * 128;
    float* krow = Ke + base * 128;
    size_t qkvrow = (size_t)(b * L_ + l0 + r) * (3 * C_);
    #pragma unroll
    for (int dd = 0; dd < 16; dd++) {
        int d = q4 * 16 + dd;
        qrow[64 + d] = fs * aq[dd];
        krow[64 + d] = ak[dd];
        qrow[d] = SCALE_ * qkv[qkvrow + h * 64 + d];
        krow[d] = qkv[qkvrow + C_ + h * 64 + d];
        Vo[base * 64 + d] = qkv[qkvrow + 2 * C_ + h * 64 + d];
    }
}

// ------------- flash attention, D_qk=128, D_v=64, no mask -------------------
#define ATTN_SMEM_FLOATS (64*132*2 + 64*64 + 64*65)
__global__ __launch_bounds__(256) void attn_kernel(
    const float* __restrict__ Qe, const float* __restrict__ Ke,
    const float* __restrict__ V, float* __restrict__ O) {
    extern __shared__ float sm[];
    float* Qs = sm;                  // 64 x 132 (padded)
    float* Ks = Qs + 64 * 132;       // 64 x 132
    float* Vs = Ks + 64 * 132;       // 64 x 64
    float* Ps = Vs + 64 * 64;        // 64 x 65
    int qt = blockIdx.x, bh = blockIdx.y;
    int tid = threadIdx.x, tx = tid & 15, ty = tid >> 4;
    const float* Qp = Qe + ((size_t)bh * L_ + qt * 64) * 128;
    const float* Kp = Ke + (size_t)bh * L_ * 128;
    const float* Vp = V + (size_t)bh * L_ * 64;

    for (int i = tid; i < 2048; i += 256) {
        int r = i >> 5, c = (i & 31) * 4;
        *(float4*)(Qs + r * 132 + c) = *(const float4*)(Qp + r * 128 + c);
    }
    float acc[4][4]; float m_[4], l_[4];
    #pragma unroll
    for (int i = 0; i < 4; i++) {
        m_[i] = -1e30f; l_[i] = 0.f;
        #pragma unroll
        for (int j = 0; j < 4; j++) acc[i][j] = 0.f;
    }
    __syncthreads();

    for (int kt = 0; kt < L_ / 64; kt++) {
        const float* Kt = Kp + (size_t)kt * 64 * 128;
        for (int i = tid; i < 2048; i += 256) {
            int r = i >> 5, c = (i & 31) * 4;
            *(float4*)(Ks + r * 132 + c) = *(const float4*)(Kt + r * 128 + c);
        }
        const float4* Vt = (const float4*)(Vp + (size_t)kt * 64 * 64);
        for (int i = tid; i < 1024; i += 256) ((float4*)Vs)[i] = Vt[i];
        __syncthreads();

        float s[4][4];
        #pragma unroll
        for (int i = 0; i < 4; i++)
            #pragma unroll
            for (int j = 0; j < 4; j++) s[i][j] = 0.f;
        #pragma unroll 4
        for (int d = 0; d < 128; d++) {
            float a[4], bb[4];
            #pragma unroll
            for (int i = 0; i < 4; i++) a[i] = Qs[(ty + 16 * i) * 132 + d];
            #pragma unroll
            for (int j = 0; j < 4; j++) bb[j] = Ks[(tx + 16 * j) * 132 + d];
            #pragma unroll
            for (int i = 0; i < 4; i++)
                #pragma unroll
                for (int j = 0; j < 4; j++) s[i][j] += a[i] * bb[j];
        }
        // online softmax per row (16 threads per row share via width-16 shuffles)
        #pragma unroll
        for (int i = 0; i < 4; i++) {
            float mx = fmaxf(fmaxf(s[i][0], s[i][1]), fmaxf(s[i][2], s[i][3]));
            #pragma unroll
            for (int o = 8; o; o >>= 1)
                mx = fmaxf(mx, __shfl_xor_sync(0xffffffffu, mx, o, 16));
            float mnew = fmaxf(m_[i], mx);
            float alpha = __expf(m_[i] - mnew);
            float rs = 0.f;
            #pragma unroll
            for (int j = 0; j < 4; j++) {
                float p = __expf(s[i][j] - mnew);
                Ps[(ty + 16 * i) * 65 + tx + 16 * j] = p;
                rs += p;
            }
            #pragma unroll
            for (int o = 8; o; o >>= 1)
                rs += __shfl_xor_sync(0xffffffffu, rs, o, 16);
            l_[i] = l_[i] * alpha + rs;
            m_[i] = mnew;
            #pragma unroll
            for (int j = 0; j < 4; j++) acc[i][j] *= alpha;
        }
        __syncthreads();
        // O += P @ V
        #pragma unroll 2
        for (int k = 0; k < 64; k++) {
            float p[4], vv[4];
            #pragma unroll
            for (int i = 0; i < 4; i++) p[i] = Ps[(ty + 16 * i) * 65 + k];
            #pragma unroll
            for (int j = 0; j < 4; j++) vv[j] = Vs[k * 64 + tx + 16 * j];
            #pragma unroll
            for (int i = 0; i < 4; i++)
                #pragma unroll
                for (int j = 0; j < 4; j++) acc[i][j] += p[i] * vv[j];
        }
        __syncthreads();
    }
    int b = bh >> 4, h = bh & 15;
    #pragma unroll
    for (int i = 0; i < 4; i++) {
        int l = qt * 64 + ty + 16 * i;
        float inv = 1.0f / l_[i];
        #pragma unroll
        for (int j = 0; j < 4; j++)
            O[((size_t)(b * L_ + l)) * C_ + h * 64 + tx + 16 * j] = acc[i][j] * inv;
    }
}

// ---------------------------------------------------------------------------
extern "C" void kernel_launch(void* const* d_in, const int* in_sizes, int n_in,
                              void* d_out, int out_size) {
    const float* x        = (const float*)d_in[0];
    const float* freqd    = (const float*)d_in[1];
    const float* qkv_w    = (const float*)d_in[2];
    const float* qkv_b    = (const float*)d_in[3];
    const float* fp_w1    = (const float*)d_in[4];
    const float* fp_b1    = (const float*)d_in[5];
    const float* fp_ln_g  = (const float*)d_in[6];
    const float* fp_ln_b  = (const float*)d_in[7];
    const float* fp_w2    = (const float*)d_in[8];
    const float* fp_b2    = (const float*)d_in[9];
    const float* wq_w     = (const float*)d_in[10];
    const float* wq_b     = (const float*)d_in[11];
    const float* wk_w     = (const float*)d_in[12];
    const float* wk_b     = (const float*)d_in[13];
    const float* out_w    = (const float*)d_in[14];
    const float* out_b    = (const float*)d_in[15];
    const float* n1_g     = (const float*)d_in[16];
    const float* n1_b     = (const float*)d_in[17];
    const float* n2_g     = (const float*)d_in[18];
    const float* n2_b     = (const float*)d_in[19];
    const float* mlp_w1   = (const float*)d_in[20];
    const float* mlp_b1   = (const float*)d_in[21];
    const float* mlp_w2   = (const float*)d_in[22];
    const float* mlp_b2   = (const float*)d_in[23];
    const float* fscale   = (const float*)d_in[24];
    float* out = (float*)d_out;

    float *p_xn, *p_qkv, *p_fbg, *p_fb2, *p_Qe, *p_Ke, *p_V, *p_O, *p_xmid, *p_xn2, *p_h;
    cudaGetSymbolAddress((void**)&p_xn,   g_xn);
    cudaGetSymbolAddress((void**)&p_qkv,  g_qkv);
    cudaGetSymbolAddress((void**)&p_fbg,  g_fbg);
    cudaGetSymbolAddress((void**)&p_fb2,  g_fb2);
    cudaGetSymbolAddress((void**)&p_Qe,   g_Qe);
    cudaGetSymbolAddress((void**)&p_Ke,   g_Ke);
    cudaGetSymbolAddress((void**)&p_V,    g_V);
    cudaGetSymbolAddress((void**)&p_O,    g_O);
    cudaGetSymbolAddress((void**)&p_xmid, g_xmid);
    cudaGetSymbolAddress((void**)&p_xn2,  g_xn2);
    cudaGetSymbolAddress((void**)&p_h,    g_h);

    cudaFuncSetAttribute(attn_kernel, cudaFuncAttributeMaxDynamicSharedMemorySize,
                         ATTN_SMEM_FLOATS * (int)sizeof(float));

    // 1. LN1
    ln_kernel<<<ROWS, 256>>>(x, n1_g, n1_b, p_xn);
    // 2. QKV projection: [4096,1024] @ [1024,3072]
    gemm_kernel<<<dim3(3 * C_ / 128, ROWS / 128), 256>>>(p_xn, qkv_w, qkv_b, nullptr,
                                                         p_qkv, ROWS, 3 * C_, C_, 0);
    // 3. freq rank-1 + LN + GELU
    fb1_kernel<<<ROWS, 256>>>(freqd, fp_w1, fp_b1, fp_ln_g, fp_ln_b, p_fbg);
    // 4. fb @ fp_w2: [4096,1024] @ [1024,1024]
    gemm_kernel<<<dim3(C_ / 128, ROWS / 128), 256>>>(p_fbg, fp_w2, fp_b2, nullptr,
                                                     p_fb2, ROWS, C_, C_, 0);
    // 5. build Q_ext/K_ext/V (fold freq attention bias into head-dim extension)
    build_ext_kernel<<<dim3(L_ / 64, B_ * H_), 256>>>(p_qkv, p_fb2, wq_w, wq_b,
                                                      wk_w, wk_b, fscale,
                                                      p_Qe, p_Ke, p_V);
    // 6. fused attention
    attn_kernel<<<dim3(L_ / 64, B_ * H_), 256,
                  ATTN_SMEM_FLOATS * sizeof(float)>>>(p_Qe, p_Ke, p_V, p_O);
    // 7. out projection + residual(x)
    gemm_kernel<<<dim3(C_ / 128, ROWS / 128), 256>>>(p_O, out_w, out_b, x,
                                                     p_xmid, ROWS, C_, C_, 0);
    // 8. LN2
    ln_kernel<<<ROWS, 256>>>(p_xmid, n2_g, n2_b, p_xn2);
    // 9. MLP up + GELU: [4096,1024] @ [1024,4096]
    gemm_kernel<<<dim3(FF_ / 128, ROWS / 128), 256>>>(p_xn2, mlp_w1, mlp_b1, nullptr,
                                                      p_h, ROWS, FF_, C_, 1);
    // 10. MLP down + residual(xmid) -> final output
    gemm_kernel<<<dim3(C_ / 128, ROWS / 128), 256>>>(p_h, mlp_w2, mlp_b2, p_xmid,
                                                     out, ROWS, C_, FF_, 0);
}

// round 3
// speedup vs baseline: 1.6426x; 1.6426x over previous
#include <cuda_runtime.h>
#include <cuda_bf16.h>
#include <cstdint>
#include <math.h>

#define B_  2
#define L_  2048
#define C_  1024
#define H_  16
#define HD_ 64
#define FF_ 4096
#define ROWS (B_*L_)          // 4096
#define SCALE_ 0.125f         // 64^-0.5
#define EPS_ 1e-5f

// ---------------- scratch (allocation-free rule: __device__ globals) --------
__device__ float g_xn  [ROWS*C_];        // LN1 out (tf32-rounded)
__device__ float g_qkv [ROWS*3*C_];      // qkv proj out
__device__ float g_fbg [ROWS*C_];        // gelu(ln(freq outer)) out (tf32-rounded)
__device__ float g_fb2 [ROWS*C_];        // fb @ fp_w2
__device__ float g_Qe  [B_*H_*L_*128];   // [SCALE*q , fs*qb]
__device__ float g_Ke  [B_*H_*L_*128];   // [k , kb]
__device__ float g_V   [B_*H_*L_*HD_];
__device__ float g_O   [ROWS*C_];        // attention out (tf32-rounded)
__device__ float g_xmid[ROWS*C_];        // after attn residual
__device__ float g_xn2 [ROWS*C_];        // LN2 out (tf32-rounded)
__device__ float g_h   [ROWS*FF_];       // mlp hidden (tf32-rounded)
// tf32-rounded weight copies
__device__ float g_w_qkv[C_*3*C_];
__device__ float g_w_fp2[C_*C_];
__device__ float g_w_out[C_*C_];
__device__ float g_w_m1 [C_*FF_];
__device__ float g_w_m2 [FF_*C_];

__device__ __forceinline__ float gelu_exact(float v) {
    return 0.5f * v * (1.0f + erff(v * 0.70710678118654752f));
}
__device__ __forceinline__ float to_tf32(float x) {
    unsigned int u;
    asm("cvt.rna.tf32.f32 %0, %1;" : "=r"(u) : "f"(x));
    return __uint_as_float(u);
}
__device__ __forceinline__ void cp16(float* smem_dst, const float* gmem_src) {
    unsigned int s = (unsigned int)__cvta_generic_to_shared(smem_dst);
    asm volatile("cp.async.cg.shared.global [%0], [%1], 16;" :: "r"(s), "l"(gmem_src));
}

// ---------------- tf32 rounding copy (weights pre-pass) ---------------------
__global__ void tf32_round_kernel(const float* __restrict__ X, float* __restrict__ Y, int n4) {
    int i = blockIdx.x * blockDim.x + threadIdx.x;
    if (i < n4) {
        float4 v = ((const float4*)X)[i];
        v.x = to_tf32(v.x); v.y = to_tf32(v.y);
        v.z = to_tf32(v.z); v.w = to_tf32(v.w);
        ((float4*)Y)[i] = v;
    }
}

// ---------------- LayerNorm (output tf32-rounded; feeds GEMM A) -------------
__global__ void ln_kernel(const float* __restrict__ X, const float* __restrict__ g,
                          const float* __restrict__ b, float* __restrict__ Y) {
    int row = blockIdx.x;
    int tid = threadIdx.x;                       // 256 threads, 1 float4 each
    const float4* xr = (const float4*)(X + (size_t)row * C_);
    float4 t = xr[tid];
    float s  = t.x + t.y + t.z + t.w;
    float sq = t.x*t.x + t.y*t.y + t.z*t.z + t.w*t.w;
    #pragma unroll
    for (int o = 16; o; o >>= 1) {
        s  += __shfl_xor_sync(0xffffffffu, s,  o);
        sq += __shfl_xor_sync(0xffffffffu, sq, o);
    }
    __shared__ float ws[8], wq[8];
    __shared__ float mean_s, rstd_s;
    int w = tid >> 5;
    if ((tid & 31) == 0) { ws[w] = s; wq[w] = sq; }
    __syncthreads();
    if (tid == 0) {
        float S = 0.f, Q = 0.f;
        #pragma unroll
        for (int i = 0; i < 8; i++) { S += ws[i]; Q += wq[i]; }
        float mean = S * (1.0f / C_);
        float var  = Q * (1.0f / C_) - mean * mean;
        mean_s = mean; rstd_s = rsqrtf(var + EPS_);
    }
    __syncthreads();
    float mean = mean_s, rstd = rstd_s;
    float4 gg = ((const float4*)g)[tid];
    float4 bb = ((const float4*)b)[tid];
    float4 o;
    o.x = to_tf32((t.x - mean) * rstd * gg.x + bb.x);
    o.y = to_tf32((t.y - mean) * rstd * gg.y + bb.y);
    o.z = to_tf32((t.z - mean) * rstd * gg.z + bb.z);
    o.w = to_tf32((t.w - mean) * rstd * gg.w + bb.w);
    ((float4*)(Y + (size_t)row * C_))[tid] = o;
}

// ------------- freq path stage 1: rank-1 outer + LN + exact GELU ------------
__global__ void fb1_kernel(const float* __restrict__ fd, const float* __restrict__ w1,
                           const float* __restrict__ b1, const float* __restrict__ g,
                           const float* __restrict__ bln, float* __restrict__ Y) {
    int row = blockIdx.x;
    int tid = threadIdx.x;
    float f = fd[row];
    float4 w = ((const float4*)w1)[tid];
    float4 bb = ((const float4*)b1)[tid];
    float4 t;
    t.x = f * w.x + bb.x; t.y = f * w.y + bb.y;
    t.z = f * w.z + bb.z; t.w = f * w.w + bb.w;
    float s  = t.x + t.y + t.z + t.w;
    float sq = t.x*t.x + t.y*t.y + t.z*t.z + t.w*t.w;
    #pragma unroll
    for (int o = 16; o; o >>= 1) {
        s  += __shfl_xor_sync(0xffffffffu, s,  o);
        sq += __shfl_xor_sync(0xffffffffu, sq, o);
    }
    __shared__ float ws[8], wqs[8];
    __shared__ float mean_s, rstd_s;
    int w5 = tid >> 5;
    if ((tid & 31) == 0) { ws[w5] = s; wqs[w5] = sq; }
    __syncthreads();
    if (tid == 0) {
        float S = 0.f, Q = 0.f;
        #pragma unroll
        for (int i = 0; i < 8; i++) { S += ws[i]; Q += wqs[i]; }
        float mean = S * (1.0f / C_);
        float var  = Q * (1.0f / C_) - mean * mean;
        mean_s = mean; rstd_s = rsqrtf(var + EPS_);
    }
    __syncthreads();
    float mean = mean_s, rstd = rstd_s;
    float4 gg = ((const float4*)g)[tid];
    float4 bl = ((const float4*)bln)[tid];
    float4 o;
    o.x = to_tf32(gelu_exact((t.x - mean) * rstd * gg.x + bl.x));
    o.y = to_tf32(gelu_exact((t.y - mean) * rstd * gg.y + bl.y));
    o.z = to_tf32(gelu_exact((t.z - mean) * rstd * gg.z + bl.z));
    o.w = to_tf32(gelu_exact((t.w - mean) * rstd * gg.w + bl.w));
    ((float4*)(Y + (size_t)row * C_))[tid] = o;
}

// ---------------- tf32 tensor-core GEMM: C = act(A@B + bias) (+R) -----------
// A [M,K] rm (tf32 values), B [K,N] rm (tf32 values). 128x128x16 CTA tile,
// 8 warps of 32x64, mma.m16n8k8.tf32, cp.async 3-stage pipeline.
// act: 0 none, 1 gelu + tf32-round output.
#define BK_ 16
#define ASTR 20        // A smem row stride (floats): conflict-free frag loads
#define BSTR 136       // B smem row stride (floats): conflict-free frag loads
#define A_ST (128*ASTR)          // 2560
#define B_ST (BK_*BSTR)          // 2176
#define STG  (A_ST + B_ST)       // 4736 floats
#define GEMM_SMEM (3*STG*4)      // 56832 bytes

__global__ __launch_bounds__(256, 1) void gemm_tc(
    const float* __restrict__ A, const float* __restrict__ Bm,
    const float* __restrict__ bias, const float* __restrict__ R,
    float* __restrict__ C, int M, int N, int K, int act) {
    extern __shared__ float sm[];
    int tid = threadIdx.x;
    int lane = tid & 31, wid = tid >> 5;
    int wm = wid & 3, wn = wid >> 2;       // 4 x 2 warp grid
    int m0 = blockIdx.y * 128, n0 = blockIdx.x * 128;

    float c[2][8][4];
    #pragma unroll
    for (int mi = 0; mi < 2; mi++)
        #pragma unroll
        for (int ni = 0; ni < 8; ni++)
            #pragma unroll
            for (int q = 0; q < 4; q++) c[mi][ni][q] = 0.f;

    int NT = K / BK_;
    // async tile issue
    auto issue = [&](int t) {
        float* As = sm + (t % 3) * STG;
        float* Bs = As + A_ST;
        int k0 = t * BK_;
        #pragma unroll
        for (int it = 0; it < 2; it++) {
            int i = tid + it * 256;
            int am = i >> 2, akc = (i & 3) * 4;
            cp16(As + am * ASTR + akc, A + (size_t)(m0 + am) * K + k0 + akc);
            int bk = i >> 5, bn = (i & 31) * 4;
            cp16(Bs + bk * BSTR + bn, Bm + (size_t)(k0 + bk) * N + n0 + bn);
        }
        asm volatile("cp.async.commit_group;");
    };
    issue(0);
    issue(1);

    int r = lane >> 2, g = lane & 3;
    for (int t = 0; t < NT; t++) {
        if (t + 1 < NT) asm volatile("cp.async.wait_group 1;");
        else            asm volatile("cp.async.wait_group 0;");
        __syncthreads();
        if (t + 2 < NT) issue(t + 2);

        const unsigned int* AsU = (const unsigned int*)(sm + (t % 3) * STG);
        const unsigned int* BsU = AsU + A_ST;
        #pragma unroll
        for (int ks = 0; ks < BK_; ks += 8) {
            unsigned int a[2][4], b[8][2];
            #pragma unroll
            for (int mi = 0; mi < 2; mi++) {
                int base = (wm * 32 + mi * 16 + r) * ASTR + ks + g;
                a[mi][0] = AsU[base];
                a[mi][1] = AsU[base + 8 * ASTR];
                a[mi][2] = AsU[base + 4];
                a[mi][3] = AsU[base + 8 * ASTR + 4];
            }
            #pragma unroll
            for (int ni = 0; ni < 8; ni++) {
                int nb = wn * 64 + ni * 8 + r;
                b[ni][0] = BsU[(ks + g) * BSTR + nb];
                b[ni][1] = BsU[(ks + g + 4) * BSTR + nb];
            }
            #pragma unroll
            for (int mi = 0; mi < 2; mi++)
                #pragma unroll
                for (int ni = 0; ni < 8; ni++) {
                    asm volatile(
                        "mma.sync.aligned.m16n8k8.row.col.f32.tf32.tf32.f32 "
                        "{%0,%1,%2,%3}, {%4,%5,%6,%7}, {%8,%9}, {%0,%1,%2,%3};"
                        : "+f"(c[mi][ni][0]), "+f"(c[mi][ni][1]),
                          "+f"(c[mi][ni][2]), "+f"(c[mi][ni][3])
                        : "r"(a[mi][0]), "r"(a[mi][1]), "r"(a[mi][2]), "r"(a[mi][3]),
                          "r"(b[ni][0]), "r"(b[ni][1]));
                }
        }
        __syncthreads();
    }

    // epilogue
    #pragma unroll
    for (int mi = 0; mi < 2; mi++) {
        int row0 = m0 + wm * 32 + mi * 16 + r;
        #pragma unroll
        for (int ni = 0; ni < 8; ni++) {
            int col = n0 + wn * 64 + ni * 8 + g * 2;
            float b0 = bias[col], b1 = bias[col + 1];
            #pragma unroll
            for (int half = 0; half < 2; half++) {
                int row = row0 + half * 8;
                float v0 = c[mi][ni][half * 2 + 0] + b0;
                float v1 = c[mi][ni][half * 2 + 1] + b1;
                if (act == 1) { v0 = to_tf32(gelu_exact(v0)); v1 = to_tf32(gelu_exact(v1)); }
                if (R) {
                    v0 += R[(size_t)row * N + col];
                    v1 += R[(size_t)row * N + col + 1];
                }
                *(float2*)(C + (size_t)row * N + col) = make_float2(v0, v1);
            }
        }
    }
}

// ------- build extended Q/K and V: fold freq bias into extra 64 dims --------
__global__ void build_ext_kernel(const float* __restrict__ qkv, const float* __restrict__ fb2,
                                 const float* __restrict__ wqw, const float* __restrict__ wqb,
                                 const float* __restrict__ wkw, const float* __restrict__ wkb,
                                 const float* __restrict__ fscale,
                                 float* __restrict__ Qe, float* __restrict__ Ke,
                                 float* __restrict__ Vo) {
    __shared__ float swq[64 * 64], swk[64 * 64], sfb[64 * 65];
    int bh = blockIdx.y;               // b*16+h
    int lt = blockIdx.x;               // 64-row tile of L
    int b = bh >> 4, h = bh & 15;
    int l0 = lt * 64;
    int tid = threadIdx.x;             // 256
    for (int i = tid; i < 4096; i += 256) { swq[i] = wqw[i]; swk[i] = wkw[i]; }
    for (int i = tid; i < 4096; i += 256) {
        int r = i >> 6, c = i & 63;
        sfb[r * 65 + c] = fb2[(size_t)(b * L_ + l0 + r) * C_ + h * 64 + c];
    }
    __syncthreads();
    int r = tid >> 2, q4 = tid & 3;
    float fs = fscale[0];
    float aq[16], ak[16];
    #pragma unroll
    for (int d = 0; d < 16; d++) { aq[d] = wqb[q4 * 16 + d]; ak[d] = wkb[q4 * 16 + d]; }
    for (int e = 0; e < 64; e++) {
        float fe = sfb[r * 65 + e];
        #pragma unroll
        for (int d = 0; d < 16; d++) {
            aq[d] += fe * swq[e * 64 + q4 * 16 + d];
            ak[d] += fe * swk[e * 64 + q4 * 16 + d];
        }
    }
    size_t base = (size_t)bh * L_ + l0 + r;
    float* qrow = Qe + base * 128;
    float* krow = Ke + base * 128;
    size_t qkvrow = (size_t)(b * L_ + l0 + r) * (3 * C_);
    #pragma unroll
    for (int dd = 0; dd < 16; dd++) {
        int d = q4 * 16 + dd;
        qrow[64 + d] = fs * aq[dd];
        krow[64 + d] = ak[dd];
        qrow[d] = SCALE_ * qkv[qkvrow + h * 64 + d];
        krow[d] = qkv[qkvrow + C_ + h * 64 + d];
        Vo[base * 64 + d] = qkv[qkvrow + 2 * C_ + h * 64 + d];
    }
}

// ------------- flash attention, D_qk=128, D_v=64, no mask -------------------
#define ATTN_SMEM_FLOATS (64*132*2 + 64*64 + 64*65)
__global__ __launch_bounds__(256) void attn_kernel(
    const float* __restrict__ Qe, const float* __restrict__ Ke,
    const float* __restrict__ V, float* __restrict__ O) {
    extern __shared__ float smA[];
    float* Qs = smA;                 // 64 x 132 (padded)
    float* Ks = Qs + 64 * 132;       // 64 x 132
    float* Vs = Ks + 64 * 132;       // 64 x 64
    float* Ps = Vs + 64 * 64;        // 64 x 65
    int qt = blockIdx.x, bh = blockIdx.y;
    int tid = threadIdx.x, tx = tid & 15, ty = tid >> 4;
    const float* Qp = Qe + ((size_t)bh * L_ + qt * 64) * 128;
    const float* Kp = Ke + (size_t)bh * L_ * 128;
    const float* Vp = V + (size_t)bh * L_ * 64;

    for (int i = tid; i < 2048; i += 256) {
        int r = i >> 5, c = (i & 31) * 4;
        *(float4*)(Qs + r * 132 + c) = *(const float4*)(Qp + r * 128 + c);
    }
    float acc[4][4]; float m_[4], l_[4];
    #pragma unroll
    for (int i = 0; i < 4; i++) {
        m_[i] = -1e30f; l_[i] = 0.f;
        #pragma unroll
        for (int j = 0; j < 4; j++) acc[i][j] = 0.f;
    }
    __syncthreads();

    for (int kt = 0; kt < L_ / 64; kt++) {
        const float* Kt = Kp + (size_t)kt * 64 * 128;
        for (int i = tid; i < 2048; i += 256) {
            int r = i >> 5, c = (i & 31) * 4;
            *(float4*)(Ks + r * 132 + c) = *(const float4*)(Kt + r * 128 + c);
        }
        const float4* Vt = (const float4*)(Vp + (size_t)kt * 64 * 64);
        for (int i = tid; i < 1024; i += 256) ((float4*)Vs)[i] = Vt[i];
        __syncthreads();

        float s[4][4];
        #pragma unroll
        for (int i = 0; i < 4; i++)
            #pragma unroll
            for (int j = 0; j < 4; j++) s[i][j] = 0.f;
        #pragma unroll 4
        for (int d = 0; d < 128; d++) {
            float a[4], bb[4];
            #pragma unroll
            for (int i = 0; i < 4; i++) a[i] = Qs[(ty + 16 * i) * 132 + d];
            #pragma unroll
            for (int j = 0; j < 4; j++) bb[j] = Ks[(tx + 16 * j) * 132 + d];
            #pragma unroll
            for (int i = 0; i < 4; i++)
                #pragma unroll
                for (int j = 0; j < 4; j++) s[i][j] += a[i] * bb[j];
        }
        #pragma unroll
        for (int i = 0; i < 4; i++) {
            float mx = fmaxf(fmaxf(s[i][0], s[i][1]), fmaxf(s[i][2], s[i][3]));
            #pragma unroll
            for (int o = 8; o; o >>= 1)
                mx = fmaxf(mx, __shfl_xor_sync(0xffffffffu, mx, o, 16));
            float mnew = fmaxf(m_[i], mx);
            float alpha = __expf(m_[i] - mnew);
            float rs = 0.f;
            #pragma unroll
            for (int j = 0; j < 4; j++) {
                float p = __expf(s[i][j] - mnew);
                Ps[(ty + 16 * i) * 65 + tx + 16 * j] = p;
                rs += p;
            }
            #pragma unroll
            for (int o = 8; o; o >>= 1)
                rs += __shfl_xor_sync(0xffffffffu, rs, o, 16);
            l_[i] = l_[i] * alpha + rs;
            m_[i] = mnew;
            #pragma unroll
            for (int j = 0; j < 4; j++) acc[i][j] *= alpha;
        }
        __syncthreads();
        #pragma unroll 2
        for (int k = 0; k < 64; k++) {
            float p[4], vv[4];
            #pragma unroll
            for (int i = 0; i < 4; i++) p[i] = Ps[(ty + 16 * i) * 65 + k];
            #pragma unroll
            for (int j = 0; j < 4; j++) vv[j] = Vs[k * 64 + tx + 16 * j];
            #pragma unroll
            for (int i = 0; i < 4; i++)
                #pragma unroll
                for (int j = 0; j < 4; j++) acc[i][j] += p[i] * vv[j];
        }
        __syncthreads();
    }
    int b = bh >> 4, h = bh & 15;
    #pragma unroll
    for (int i = 0; i < 4; i++) {
        int l = qt * 64 + ty + 16 * i;
        float inv = 1.0f / l_[i];
        #pragma unroll
        for (int j = 0; j < 4; j++)
            O[((size_t)(b * L_ + l)) * C_ + h * 64 + tx + 16 * j] =
                to_tf32(acc[i][j] * inv);
    }
}

// ---------------------------------------------------------------------------
extern "C" void kernel_launch(void* const* d_in, const int* in_sizes, int n_in,
                              void* d_out, int out_size) {
    const float* x        = (const float*)d_in[0];
    const float* freqd    = (const float*)d_in[1];
    const float* qkv_w    = (const float*)d_in[2];
    const float* qkv_b    = (const float*)d_in[3];
    const float* fp_w1    = (const float*)d_in[4];
    const float* fp_b1    = (const float*)d_in[5];
    const float* fp_ln_g  = (const float*)d_in[6];
    const float* fp_ln_b  = (const float*)d_in[7];
    const float* fp_w2    = (const float*)d_in[8];
    const float* fp_b2    = (const float*)d_in[9];
    const float* wq_w     = (const float*)d_in[10];
    const float* wq_b     = (const float*)d_in[11];
    const float* wk_w     = (const float*)d_in[12];
    const float* wk_b     = (const float*)d_in[13];
    const float* out_w    = (const float*)d_in[14];
    const float* out_b    = (const float*)d_in[15];
    const float* n1_g     = (const float*)d_in[16];
    const float* n1_b     = (const float*)d_in[17];
    const float* n2_g     = (const float*)d_in[18];
    const float* n2_b     = (const float*)d_in[19];
    const float* mlp_w1   = (const float*)d_in[20];
    const float* mlp_b1   = (const float*)d_in[21];
    const float* mlp_w2   = (const float*)d_in[22];
    const float* mlp_b2   = (const float*)d_in[23];
    const float* fscale   = (const float*)d_in[24];
    float* out = (float*)d_out;

    float *p_xn, *p_qkv, *p_fbg, *p_fb2, *p_Qe, *p_Ke, *p_V, *p_O, *p_xmid, *p_xn2, *p_h;
    float *pw_qkv, *pw_fp2, *pw_out, *pw_m1, *pw_m2;
    cudaGetSymbolAddress((void**)&p_xn,   g_xn);
    cudaGetSymbolAddress((void**)&p_qkv,  g_qkv);
    cudaGetSymbolAddress((void**)&p_fbg,  g_fbg);
    cudaGetSymbolAddress((void**)&p_fb2,  g_fb2);
    cudaGetSymbolAddress((void**)&p_Qe,   g_Qe);
    cudaGetSymbolAddress((void**)&p_Ke,   g_Ke);
    cudaGetSymbolAddress((void**)&p_V,    g_V);
    cudaGetSymbolAddress((void**)&p_O,    g_O);
    cudaGetSymbolAddress((void**)&p_xmid, g_xmid);
    cudaGetSymbolAddress((void**)&p_xn2,  g_xn2);
    cudaGetSymbolAddress((void**)&p_h,    g_h);
    cudaGetSymbolAddress((void**)&pw_qkv, g_w_qkv);
    cudaGetSymbolAddress((void**)&pw_fp2, g_w_fp2);
    cudaGetSymbolAddress((void**)&pw_out, g_w_out);
    cudaGetSymbolAddress((void**)&pw_m1,  g_w_m1);
    cudaGetSymbolAddress((void**)&pw_m2,  g_w_m2);

    cudaFuncSetAttribute(attn_kernel, cudaFuncAttributeMaxDynamicSharedMemorySize,
                         ATTN_SMEM_FLOATS * (int)sizeof(float));
    cudaFuncSetAttribute(gemm_tc, cudaFuncAttributeMaxDynamicSharedMemorySize,
                         GEMM_SMEM);

    // 0. weight tf32 pre-rounding
    tf32_round_kernel<<<(3*C_*C_/4 + 255)/256, 256>>>(qkv_w,  pw_qkv, 3*C_*C_/4);
    tf32_round_kernel<<<(C_*C_/4   + 255)/256, 256>>>(fp_w2,  pw_fp2, C_*C_/4);
    tf32_round_kernel<<<(C_*C_/4   + 255)/256, 256>>>(out_w,  pw_out, C_*C_/4);
    tf32_round_kernel<<<(C_*FF_/4  + 255)/256, 256>>>(mlp_w1, pw_m1,  C_*FF_/4);
    tf32_round_kernel<<<(FF_*C_/4  + 255)/256, 256>>>(mlp_w2, pw_m2,  FF_*C_/4);

    // 1. LN1 (tf32-rounded output)
    ln_kernel<<<ROWS, 256>>>(x, n1_g, n1_b, p_xn);
    // 2. QKV projection
    gemm_tc<<<dim3(3 * C_ / 128, ROWS / 128), 256, GEMM_SMEM>>>(
        p_xn, pw_qkv, qkv_b, nullptr, p_qkv, ROWS, 3 * C_, C_, 0);
    // 3. freq rank-1 + LN + GELU (tf32-rounded)
    fb1_kernel<<<ROWS, 256>>>(freqd, fp_w1, fp_b1, fp_ln_g, fp_ln_b, p_fbg);
    // 4. fb @ fp_w2
    gemm_tc<<<dim3(C_ / 128, ROWS / 128), 256, GEMM_SMEM>>>(
        p_fbg, pw_fp2, fp_b2, nullptr, p_fb2, ROWS, C_, C_, 0);
    // 5. build extended Q/K and V
    build_ext_kernel<<<dim3(L_ / 64, B_ * H_), 256>>>(p_qkv, p_fb2, wq_w, wq_b,
                                                      wk_w, wk_b, fscale,
                                                      p_Qe, p_Ke, p_V);
    // 6. fused attention (fp32 SIMT, O tf32-rounded)
    attn_kernel<<<dim3(L_ / 64, B_ * H_), 256,
                  ATTN_SMEM_FLOATS * sizeof(float)>>>(p_Qe, p_Ke, p_V, p_O);
    // 7. out projection + residual(x)
    gemm_tc<<<dim3(C_ / 128, ROWS / 128), 256, GEMM_SMEM>>>(
        p_O, pw_out, out_b, x, p_xmid, ROWS, C_, C_, 0);
    // 8. LN2
    ln_kernel<<<ROWS, 256>>>(p_xmid, n2_g, n2_b, p_xn2);
    // 9. MLP up + GELU (tf32-rounded hidden)
    gemm_tc<<<dim3(FF_ / 128, ROWS / 128), 256, GEMM_SMEM>>>(
        p_xn2, pw_m1, mlp_b1, nullptr, p_h, ROWS, FF_, C_, 1);
    // 10. MLP down + residual(xmid) -> final output
    gemm_tc<<<dim3(C_ / 128, ROWS / 128), 256, GEMM_SMEM>>>(
        p_h, pw_m2, mlp_b2, p_xmid, out, ROWS, C_, FF_, 0);
}

// round 4
// speedup vs baseline: 2.8123x; 1.7121x over previous
#include <cuda_runtime.h>
#include <cuda_bf16.h>
#include <cstdint>
#include <math.h>

#define B_  2
#define L_  2048
#define C_  1024
#define H_  16
#define HD_ 64
#define FF_ 4096
#define ROWS (B_*L_)          // 4096
#define SCALE_ 0.125f         // 64^-0.5
#define EPS_ 1e-5f

// ---------------- scratch (allocation-free rule: __device__ globals) --------
__device__ float g_xn  [ROWS*C_];
__device__ float g_qkv [ROWS*3*C_];
__device__ float g_fbg [ROWS*C_];
__device__ float g_fb2 [ROWS*C_];
__device__ float g_Qe  [B_*H_*L_*128];   // [SCALE*q , fs*qb] (tf32)
__device__ float g_Ke  [B_*H_*L_*128];   // [k , kb] (tf32)
__device__ float g_V   [B_*H_*L_*HD_];   // (tf32)
__device__ float g_O   [ROWS*C_];
__device__ float g_xmid[ROWS*C_];
__device__ float g_xn2 [ROWS*C_];
__device__ float g_h   [ROWS*FF_];
// tf32-rounded weight copies
__device__ float g_w_qkv[C_*3*C_];
__device__ float g_w_fp2[C_*C_];
__device__ float g_w_out[C_*C_];
__device__ float g_w_m1 [C_*FF_];
__device__ float g_w_m2 [FF_*C_];

__device__ __forceinline__ float gelu_exact(float v) {
    return 0.5f * v * (1.0f + erff(v * 0.70710678118654752f));
}
__device__ __forceinline__ float to_tf32(float x) {
    unsigned int u;
    asm("cvt.rna.tf32.f32 %0, %1;" : "=r"(u) : "f"(x));
    return __uint_as_float(u);
}
__device__ __forceinline__ void cp16(float* smem_dst, const float* gmem_src) {
    unsigned int s = (unsigned int)__cvta_generic_to_shared(smem_dst);
    asm volatile("cp.async.cg.shared.global [%0], [%1], 16;" :: "r"(s), "l"(gmem_src));
}
#define MMA_TF32(c0,c1,c2,c3,a0,a1,a2,a3,b0,b1) \
    asm volatile("mma.sync.aligned.m16n8k8.row.col.f32.tf32.tf32.f32 " \
        "{%0,%1,%2,%3}, {%4,%5,%6,%7}, {%8,%9}, {%0,%1,%2,%3};" \
        : "+f"(c0), "+f"(c1), "+f"(c2), "+f"(c3) \
        : "r"(a0), "r"(a1), "r"(a2), "r"(a3), "r"(b0), "r"(b1))

// ---------------- tf32 rounding copy (weights pre-pass) ---------------------
__global__ void tf32_round_kernel(const float* __restrict__ X, float* __restrict__ Y, int n4) {
    int i = blockIdx.x * blockDim.x + threadIdx.x;
    if (i < n4) {
        float4 v = ((const float4*)X)[i];
        v.x = to_tf32(v.x); v.y = to_tf32(v.y);
        v.z = to_tf32(v.z); v.w = to_tf32(v.w);
        ((float4*)Y)[i] = v;
    }
}

// ---------------- LayerNorm (output tf32-rounded; feeds GEMM A) -------------
__global__ void ln_kernel(const float* __restrict__ X, const float* __restrict__ g,
                          const float* __restrict__ b, float* __restrict__ Y) {
    int row = blockIdx.x;
    int tid = threadIdx.x;
    const float4* xr = (const float4*)(X + (size_t)row * C_);
    float4 t = xr[tid];
    float s  = t.x + t.y + t.z + t.w;
    float sq = t.x*t.x + t.y*t.y + t.z*t.z + t.w*t.w;
    #pragma unroll
    for (int o = 16; o; o >>= 1) {
        s  += __shfl_xor_sync(0xffffffffu, s,  o);
        sq += __shfl_xor_sync(0xffffffffu, sq, o);
    }
    __shared__ float ws[8], wq[8];
    __shared__ float mean_s, rstd_s;
    int w = tid >> 5;
    if ((tid & 31) == 0) { ws[w] = s; wq[w] = sq; }
    __syncthreads();
    if (tid == 0) {
        float S = 0.f, Q = 0.f;
        #pragma unroll
        for (int i = 0; i < 8; i++) { S += ws[i]; Q += wq[i]; }
        float mean = S * (1.0f / C_);
        float var  = Q * (1.0f / C_) - mean * mean;
        mean_s = mean; rstd_s = rsqrtf(var + EPS_);
    }
    __syncthreads();
    float mean = mean_s, rstd = rstd_s;
    float4 gg = ((const float4*)g)[tid];
    float4 bb = ((const float4*)b)[tid];
    float4 o;
    o.x = to_tf32((t.x - mean) * rstd * gg.x + bb.x);
    o.y = to_tf32((t.y - mean) * rstd * gg.y + bb.y);
    o.z = to_tf32((t.z - mean) * rstd * gg.z + bb.z);
    o.w = to_tf32((t.w - mean) * rstd * gg.w + bb.w);
    ((float4*)(Y + (size_t)row * C_))[tid] = o;
}

// ------------- freq path stage 1: rank-1 outer + LN + exact GELU ------------
__global__ void fb1_kernel(const float* __restrict__ fd, const float* __restrict__ w1,
                           const float* __restrict__ b1, const float* __restrict__ g,
                           const float* __restrict__ bln, float* __restrict__ Y) {
    int row = blockIdx.x;
    int tid = threadIdx.x;
    float f = fd[row];
    float4 w = ((const float4*)w1)[tid];
    float4 bb = ((const float4*)b1)[tid];
    float4 t;
    t.x = f * w.x + bb.x; t.y = f * w.y + bb.y;
    t.z = f * w.z + bb.z; t.w = f * w.w + bb.w;
    float s  = t.x + t.y + t.z + t.w;
    float sq = t.x*t.x + t.y*t.y + t.z*t.z + t.w*t.w;
    #pragma unroll
    for (int o = 16; o; o >>= 1) {
        s  += __shfl_xor_sync(0xffffffffu, s,  o);
        sq += __shfl_xor_sync(0xffffffffu, sq, o);
    }
    __shared__ float ws[8], wqs[8];
    __shared__ float mean_s, rstd_s;
    int w5 = tid >> 5;
    if ((tid & 31) == 0) { ws[w5] = s; wqs[w5] = sq; }
    __syncthreads();
    if (tid == 0) {
        float S = 0.f, Q = 0.f;
        #pragma unroll
        for (int i = 0; i < 8; i++) { S += ws[i]; Q += wqs[i]; }
        float mean = S * (1.0f / C_);
        float var  = Q * (1.0f / C_) - mean * mean;
        mean_s = mean; rstd_s = rsqrtf(var + EPS_);
    }
    __syncthreads();
    float mean = mean_s, rstd = rstd_s;
    float4 gg = ((const float4*)g)[tid];
    float4 bl = ((const float4*)bln)[tid];
    float4 o;
    o.x = to_tf32(gelu_exact((t.x - mean) * rstd * gg.x + bl.x));
    o.y = to_tf32(gelu_exact((t.y - mean) * rstd * gg.y + bl.y));
    o.z = to_tf32(gelu_exact((t.z - mean) * rstd * gg.z + bl.z));
    o.w = to_tf32(gelu_exact((t.w - mean) * rstd * gg.w + bl.w));
    ((float4*)(Y + (size_t)row * C_))[tid] = o;
}

// ---------------- tf32 tensor-core GEMM (unchanged from R3) -----------------
#define BK_ 16
#define ASTR 20
#define BSTR 136
#define A_ST (128*ASTR)
#define B_ST (BK_*BSTR)
#define STG  (A_ST + B_ST)
#define GEMM_SMEM (3*STG*4)

__global__ __launch_bounds__(256, 1) void gemm_tc(
    const float* __restrict__ A, const float* __restrict__ Bm,
    const float* __restrict__ bias, const float* __restrict__ R,
    float* __restrict__ C, int M, int N, int K, int act) {
    extern __shared__ float sm[];
    int tid = threadIdx.x;
    int lane = tid & 31, wid = tid >> 5;
    int wm = wid & 3, wn = wid >> 2;
    int m0 = blockIdx.y * 128, n0 = blockIdx.x * 128;

    float c[2][8][4];
    #pragma unroll
    for (int mi = 0; mi < 2; mi++)
        #pragma unroll
        for (int ni = 0; ni < 8; ni++)
            #pragma unroll
            for (int q = 0; q < 4; q++) c[mi][ni][q] = 0.f;

    int NT = K / BK_;
    auto issue = [&](int t) {
        float* As = sm + (t % 3) * STG;
        float* Bs = As + A_ST;
        int k0 = t * BK_;
        #pragma unroll
        for (int it = 0; it < 2; it++) {
            int i = tid + it * 256;
            int am = i >> 2, akc = (i & 3) * 4;
            cp16(As + am * ASTR + akc, A + (size_t)(m0 + am) * K + k0 + akc);
            int bk = i >> 5, bn = (i & 31) * 4;
            cp16(Bs + bk * BSTR + bn, Bm + (size_t)(k0 + bk) * N + n0 + bn);
        }
        asm volatile("cp.async.commit_group;");
    };
    issue(0);
    issue(1);

    int r = lane >> 2, g = lane & 3;
    for (int t = 0; t < NT; t++) {
        if (t + 1 < NT) asm volatile("cp.async.wait_group 1;");
        else            asm volatile("cp.async.wait_group 0;");
        __syncthreads();
        if (t + 2 < NT) issue(t + 2);

        const unsigned int* AsU = (const unsigned int*)(sm + (t % 3) * STG);
        const unsigned int* BsU = AsU + A_ST;
        #pragma unroll
        for (int ks = 0; ks < BK_; ks += 8) {
            unsigned int a[2][4], b[8][2];
            #pragma unroll
            for (int mi = 0; mi < 2; mi++) {
                int base = (wm * 32 + mi * 16 + r) * ASTR + ks + g;
                a[mi][0] = AsU[base];
                a[mi][1] = AsU[base + 8 * ASTR];
                a[mi][2] = AsU[base + 4];
                a[mi][3] = AsU[base + 8 * ASTR + 4];
            }
            #pragma unroll
            for (int ni = 0; ni < 8; ni++) {
                int nb = wn * 64 + ni * 8 + r;
                b[ni][0] = BsU[(ks + g) * BSTR + nb];
                b[ni][1] = BsU[(ks + g + 4) * BSTR + nb];
            }
            #pragma unroll
            for (int mi = 0; mi < 2; mi++)
                #pragma unroll
                for (int ni = 0; ni < 8; ni++)
                    MMA_TF32(c[mi][ni][0], c[mi][ni][1], c[mi][ni][2], c[mi][ni][3],
                             a[mi][0], a[mi][1], a[mi][2], a[mi][3],
                             b[ni][0], b[ni][1]);
        }
        __syncthreads();
    }

    #pragma unroll
    for (int mi = 0; mi < 2; mi++) {
        int row0 = m0 + wm * 32 + mi * 16 + r;
        #pragma unroll
        for (int ni = 0; ni < 8; ni++) {
            int col = n0 + wn * 64 + ni * 8 + g * 2;
            float b0 = bias[col], b1 = bias[col + 1];
            #pragma unroll
            for (int half = 0; half < 2; half++) {
                int row = row0 + half * 8;
                float v0 = c[mi][ni][half * 2 + 0] + b0;
                float v1 = c[mi][ni][half * 2 + 1] + b1;
                if (act == 1) { v0 = to_tf32(gelu_exact(v0)); v1 = to_tf32(gelu_exact(v1)); }
                if (R) {
                    v0 += R[(size_t)row * N + col];
                    v1 += R[(size_t)row * N + col + 1];
                }
                *(float2*)(C + (size_t)row * N + col) = make_float2(v0, v1);
            }
        }
    }
}

// ------- build extended Q/K and V (tf32-rounded outputs for mma attn) -------
__global__ void build_ext_kernel(const float* __restrict__ qkv, const float* __restrict__ fb2,
                                 const float* __restrict__ wqw, const float* __restrict__ wqb,
                                 const float* __restrict__ wkw, const float* __restrict__ wkb,
                                 const float* __restrict__ fscale,
                                 float* __restrict__ Qe, float* __restrict__ Ke,
                                 float* __restrict__ Vo) {
    __shared__ float swq[64 * 64], swk[64 * 64], sfb[64 * 65];
    int bh = blockIdx.y;
    int lt = blockIdx.x;
    int b = bh >> 4, h = bh & 15;
    int l0 = lt * 64;
    int tid = threadIdx.x;
    for (int i = tid; i < 4096; i += 256) { swq[i] = wqw[i]; swk[i] = wkw[i]; }
    for (int i = tid; i < 4096; i += 256) {
        int r = i >> 6, c = i & 63;
        sfb[r * 65 + c] = fb2[(size_t)(b * L_ + l0 + r) * C_ + h * 64 + c];
    }
    __syncthreads();
    int r = tid >> 2, q4 = tid & 3;
    float fs = fscale[0];
    float aq[16], ak[16];
    #pragma unroll
    for (int d = 0; d < 16; d++) { aq[d] = wqb[q4 * 16 + d]; ak[d] = wkb[q4 * 16 + d]; }
    for (int e = 0; e < 64; e++) {
        float fe = sfb[r * 65 + e];
        #pragma unroll
        for (int d = 0; d < 16; d++) {
            aq[d] += fe * swq[e * 64 + q4 * 16 + d];
            ak[d] += fe * swk[e * 64 + q4 * 16 + d];
        }
    }
    size_t base = (size_t)bh * L_ + l0 + r;
    float* qrow = Qe + base * 128;
    float* krow = Ke + base * 128;
    size_t qkvrow = (size_t)(b * L_ + l0 + r) * (3 * C_);
    #pragma unroll
    for (int dd = 0; dd < 16; dd++) {
        int d = q4 * 16 + dd;
        qrow[64 + d] = to_tf32(fs * aq[dd]);
        krow[64 + d] = to_tf32(ak[dd]);
        qrow[d] = to_tf32(SCALE_ * qkv[qkvrow + h * 64 + d]);
        krow[d] = to_tf32(qkv[qkvrow + C_ + h * 64 + d]);
        Vo[base * 64 + d] = to_tf32(qkv[qkvrow + 2 * C_ + h * 64 + d]);
    }
}

// ------------- tensor-core flash attention, D_qk=128, D_v=64 ----------------
// CTA: 128 q-rows, 8 warps (16 rows each). KV tile = 64, double-buffered.
#define QSTR 132
#define KSTR 132
#define VSTR 68
#define PSTR 68
#define ATTN_SM_FLOATS (128*QSTR + 2*64*KSTR + 2*64*VSTR)   // 42496 floats
__global__ __launch_bounds__(256, 1) void attn_tc(
    const float* __restrict__ Qe, const float* __restrict__ Ke,
    const float* __restrict__ V, float* __restrict__ O) {
    extern __shared__ float sm[];
    float* Qs  = sm;                       // 128 x 132; reused as Ps (128 x 68)
    float* Ks0 = sm + 128 * QSTR;          // 2 x 64 x 132
    float* Vs0 = Ks0 + 2 * 64 * KSTR;      // 2 x 64 x 68
    int qt = blockIdx.x, bh = blockIdx.y;
    int tid = threadIdx.x, lane = tid & 31, wid = tid >> 5;
    int r = lane >> 2, g = lane & 3;
    const float* Qp = Qe + ((size_t)bh * L_ + qt * 128) * 128;
    const float* Kp = Ke + (size_t)bh * L_ * 128;
    const float* Vp = V + (size_t)bh * L_ * 64;

    auto issueKV = [&](int t) {
        float* Ks = Ks0 + (t & 1) * 64 * KSTR;
        float* Vs = Vs0 + (t & 1) * 64 * VSTR;
        const float* Kt = Kp + (size_t)t * 64 * 128;
        const float* Vt = Vp + (size_t)t * 64 * 64;
        #pragma unroll
        for (int it = 0; it < 8; it++) {
            int i = tid + it * 256;
            int rr = i >> 5, cc = (i & 31) * 4;
            cp16(Ks + rr * KSTR + cc, Kt + rr * 128 + cc);
        }
        #pragma unroll
        for (int it = 0; it < 4; it++) {
            int i = tid + it * 256;
            int rr = i >> 4, cc = (i & 15) * 4;
            cp16(Vs + rr * VSTR + cc, Vt + rr * 64 + cc);
        }
        asm volatile("cp.async.commit_group;");
    };
    issueKV(0);

    // cooperative Q load, then Q fragments to registers
    for (int i = tid; i < 4096; i += 256) {
        int rr = i >> 5, cc = (i & 31) * 4;
        *(float4*)(Qs + rr * QSTR + cc) = *(const float4*)(Qp + rr * 128 + cc);
    }
    __syncthreads();
    unsigned int qf[16][4];
    const unsigned int* QsU = (const unsigned int*)Qs;
    #pragma unroll
    for (int ks = 0; ks < 16; ks++) {
        int base = (wid * 16 + r) * QSTR + ks * 8 + g;
        qf[ks][0] = QsU[base];
        qf[ks][1] = QsU[base + 8 * QSTR];
        qf[ks][2] = QsU[base + 4];
        qf[ks][3] = QsU[base + 8 * QSTR + 4];
    }
    __syncthreads();           // Qs now reusable as Ps
    float* Ps = Qs;
    unsigned int* PsU = (unsigned int*)Ps;

    float o[8][4];
    #pragma unroll
    for (int ni = 0; ni < 8; ni++)
        #pragma unroll
        for (int q = 0; q < 4; q++) o[ni][q] = 0.f;
    float m0 = -1e30f, m1 = -1e30f, l0 = 0.f, l1 = 0.f;

    for (int t = 0; t < L_ / 64; t++) {
        if (t + 1 < L_ / 64) {
            issueKV(t + 1);
            asm volatile("cp.async.wait_group 1;");
        } else {
            asm volatile("cp.async.wait_group 0;");
        }
        __syncthreads();
        const unsigned int* KsU = (const unsigned int*)(Ks0 + (t & 1) * 64 * KSTR);
        const unsigned int* VsU = (const unsigned int*)(Vs0 + (t & 1) * 64 * VSTR);

        // S = Q @ K^T  (16 k-steps of 8)
        float c[8][4];
        #pragma unroll
        for (int ni = 0; ni < 8; ni++)
            #pragma unroll
            for (int q = 0; q < 4; q++) c[ni][q] = 0.f;
        #pragma unroll
        for (int ks = 0; ks < 16; ks++) {
            unsigned int b[8][2];
            #pragma unroll
            for (int ni = 0; ni < 8; ni++) {
                int nb = ni * 8 + r;
                b[ni][0] = KsU[nb * KSTR + ks * 8 + g];
                b[ni][1] = KsU[nb * KSTR + ks * 8 + g + 4];
            }
            #pragma unroll
            for (int ni = 0; ni < 8; ni++)
                MMA_TF32(c[ni][0], c[ni][1], c[ni][2], c[ni][3],
                         qf[ks][0], qf[ks][1], qf[ks][2], qf[ks][3],
                         b[ni][0], b[ni][1]);
        }

        // online softmax: rows (wid*16 + r) and (+8); quad lanes share a row
        float mx0 = -1e30f, mx1 = -1e30f;
        #pragma unroll
        for (int ni = 0; ni < 8; ni++) {
            mx0 = fmaxf(mx0, fmaxf(c[ni][0], c[ni][1]));
            mx1 = fmaxf(mx1, fmaxf(c[ni][2], c[ni][3]));
        }
        #pragma unroll
        for (int ofs = 1; ofs <= 2; ofs <<= 1) {
            mx0 = fmaxf(mx0, __shfl_xor_sync(0xffffffffu, mx0, ofs));
            mx1 = fmaxf(mx1, __shfl_xor_sync(0xffffffffu, mx1, ofs));
        }
        float mn0 = fmaxf(m0, mx0), mn1 = fmaxf(m1, mx1);
        float al0 = __expf(m0 - mn0), al1 = __expf(m1 - mn1);
        float rs0 = 0.f, rs1 = 0.f;
        int prow0 = (wid * 16 + r) * PSTR + 2 * g;
        int prow1 = prow0 + 8 * PSTR;
        #pragma unroll
        for (int ni = 0; ni < 8; ni++) {
            float p0 = __expf(c[ni][0] - mn0);
            float p1 = __expf(c[ni][1] - mn0);
            float p2 = __expf(c[ni][2] - mn1);
            float p3 = __expf(c[ni][3] - mn1);
            rs0 += p0 + p1; rs1 += p2 + p3;
            *(float2*)(Ps + prow0 + ni * 8) = make_float2(to_tf32(p0), to_tf32(p1));
            *(float2*)(Ps + prow1 + ni * 8) = make_float2(to_tf32(p2), to_tf32(p3));
        }
        #pragma unroll
        for (int ofs = 1; ofs <= 2; ofs <<= 1) {
            rs0 += __shfl_xor_sync(0xffffffffu, rs0, ofs);
            rs1 += __shfl_xor_sync(0xffffffffu, rs1, ofs);
        }
        l0 = l0 * al0 + rs0; l1 = l1 * al1 + rs1;
        m0 = mn0; m1 = mn1;
        #pragma unroll
        for (int ni = 0; ni < 8; ni++) {
            o[ni][0] *= al0; o[ni][1] *= al0;
            o[ni][2] *= al1; o[ni][3] *= al1;
        }
        __syncwarp();          // P visible within warp (rows are warp-private)

        // O += P @ V  (8 k-steps of 8 over 64 keys)
        #pragma unroll
        for (int ks = 0; ks < 8; ks++) {
            unsigned int a[4], b[8][2];
            int abase = (wid * 16 + r) * PSTR + ks * 8 + g;
            a[0] = PsU[abase];
            a[1] = PsU[abase + 8 * PSTR];
            a[2] = PsU[abase + 4];
            a[3] = PsU[abase + 8 * PSTR + 4];
            #pragma unroll
            for (int ni = 0; ni < 8; ni++) {
                b[ni][0] = VsU[(ks * 8 + g) * VSTR + ni * 8 + r];
                b[ni][1] = VsU[(ks * 8 + g + 4) * VSTR + ni * 8 + r];
            }
            #pragma unroll
            for (int ni = 0; ni < 8; ni++)
                MMA_TF32(o[ni][0], o[ni][1], o[ni][2], o[ni][3],
                         a[0], a[1], a[2], a[3], b[ni][0], b[ni][1]);
        }
        __syncthreads();       // protect K/V buffers before re-issue
    }

    // write O (normalized, tf32-rounded; feeds out-proj GEMM)
    int b = bh >> 4, h = bh & 15;
    int l0row = qt * 128 + wid * 16 + r;
    float inv0 = 1.0f / l0, inv1 = 1.0f / l1;
    #pragma unroll
    for (int ni = 0; ni < 8; ni++) {
        int col = h * 64 + ni * 8 + 2 * g;
        *(float2*)(O + (size_t)(b * L_ + l0row) * C_ + col) =
            make_float2(to_tf32(o[ni][0] * inv0), to_tf32(o[ni][1] * inv0));
        *(float2*)(O + (size_t)(b * L_ + l0row + 8) * C_ + col) =
            make_float2(to_tf32(o[ni][2] * inv1), to_tf32(o[ni][3] * inv1));
    }
}

// ---------------------------------------------------------------------------
extern "C" void kernel_launch(void* const* d_in, const int* in_sizes, int n_in,
                              void* d_out, int out_size) {
    const float* x        = (const float*)d_in[0];
    const float* freqd    = (const float*)d_in[1];
    const float* qkv_w    = (const float*)d_in[2];
    const float* qkv_b    = (const float*)d_in[3];
    const float* fp_w1    = (const float*)d_in[4];
    const float* fp_b1    = (const float*)d_in[5];
    const float* fp_ln_g  = (const float*)d_in[6];
    const float* fp_ln_b  = (const float*)d_in[7];
    const float* fp_w2    = (const float*)d_in[8];
    const float* fp_b2    = (const float*)d_in[9];
    const float* wq_w     = (const float*)d_in[10];
    const float* wq_b     = (const float*)d_in[11];
    const float* wk_w     = (const float*)d_in[12];
    const float* wk_b     = (const float*)d_in[13];
    const float* out_w    = (const float*)d_in[14];
    const float* out_b    = (const float*)d_in[15];
    const float* n1_g     = (const float*)d_in[16];
    const float* n1_b     = (const float*)d_in[17];
    const float* n2_g     = (const float*)d_in[18];
    const float* n2_b     = (const float*)d_in[19];
    const float* mlp_w1   = (const float*)d_in[20];
    const float* mlp_b1   = (const float*)d_in[21];
    const float* mlp_w2   = (const float*)d_in[22];
    const float* mlp_b2   = (const float*)d_in[23];
    const float* fscale   = (const float*)d_in[24];
    float* out = (float*)d_out;

    float *p_xn, *p_qkv, *p_fbg, *p_fb2, *p_Qe, *p_Ke, *p_V, *p_O, *p_xmid, *p_xn2, *p_h;
    float *pw_qkv, *pw_fp2, *pw_out, *pw_m1, *pw_m2;
    cudaGetSymbolAddress((void**)&p_xn,   g_xn);
    cudaGetSymbolAddress((void**)&p_qkv,  g_qkv);
    cudaGetSymbolAddress((void**)&p_fbg,  g_fbg);
    cudaGetSymbolAddress((void**)&p_fb2,  g_fb2);
    cudaGetSymbolAddress((void**)&p_Qe,   g_Qe);
    cudaGetSymbolAddress((void**)&p_Ke,   g_Ke);
    cudaGetSymbolAddress((void**)&p_V,    g_V);
    cudaGetSymbolAddress((void**)&p_O,    g_O);
    cudaGetSymbolAddress((void**)&p_xmid, g_xmid);
    cudaGetSymbolAddress((void**)&p_xn2,  g_xn2);
    cudaGetSymbolAddress((void**)&p_h,    g_h);
    cudaGetSymbolAddress((void**)&pw_qkv, g_w_qkv);
    cudaGetSymbolAddress((void**)&pw_fp2, g_w_fp2);
    cudaGetSymbolAddress((void**)&pw_out, g_w_out);
    cudaGetSymbolAddress((void**)&pw_m1,  g_w_m1);
    cudaGetSymbolAddress((void**)&pw_m2,  g_w_m2);

    cudaFuncSetAttribute(gemm_tc, cudaFuncAttributeMaxDynamicSharedMemorySize, GEMM_SMEM);
    cudaFuncSetAttribute(attn_tc, cudaFuncAttributeMaxDynamicSharedMemorySize,
                         ATTN_SM_FLOATS * (int)sizeof(float));

    // 0. weight tf32 pre-rounding
    tf32_round_kernel<<<(3*C_*C_/4 + 255)/256, 256>>>(qkv_w,  pw_qkv, 3*C_*C_/4);
    tf32_round_kernel<<<(C_*C_/4   + 255)/256, 256>>>(fp_w2,  pw_fp2, C_*C_/4);
    tf32_round_kernel<<<(C_*C_/4   + 255)/256, 256>>>(out_w,  pw_out, C_*C_/4);
    tf32_round_kernel<<<(C_*FF_/4  + 255)/256, 256>>>(mlp_w1, pw_m1,  C_*FF_/4);
    tf32_round_kernel<<<(FF_*C_/4  + 255)/256, 256>>>(mlp_w2, pw_m2,  FF_*C_/4);

    // 1. LN1
    ln_kernel<<<ROWS, 256>>>(x, n1_g, n1_b, p_xn);
    // 2. QKV projection
    gemm_tc<<<dim3(3 * C_ / 128, ROWS / 128), 256, GEMM_SMEM>>>(
        p_xn, pw_qkv, qkv_b, nullptr, p_qkv, ROWS, 3 * C_, C_, 0);
    // 3. freq rank-1 + LN + GELU
    fb1_kernel<<<ROWS, 256>>>(freqd, fp_w1, fp_b1, fp_ln_g, fp_ln_b, p_fbg);
    // 4. fb @ fp_w2
    gemm_tc<<<dim3(C_ / 128, ROWS / 128), 256, GEMM_SMEM>>>(
        p_fbg, pw_fp2, fp_b2, nullptr, p_fb2, ROWS, C_, C_, 0);
    // 5. build extended Q/K and V (tf32)
    build_ext_kernel<<<dim3(L_ / 64, B_ * H_), 256>>>(p_qkv, p_fb2, wq_w, wq_b,
                                                      wk_w, wk_b, fscale,
                                                      p_Qe, p_Ke, p_V);
    // 6. tensor-core flash attention
    attn_tc<<<dim3(L_ / 128, B_ * H_), 256,
              ATTN_SM_FLOATS * sizeof(float)>>>(p_Qe, p_Ke, p_V, p_O);
    // 7. out projection + residual(x)
    gemm_tc<<<dim3(C_ / 128, ROWS / 128), 256, GEMM_SMEM>>>(
        p_O, pw_out, out_b, x, p_xmid, ROWS, C_, C_, 0);
    // 8. LN2
    ln_kernel<<<ROWS, 256>>>(p_xmid, n2_g, n2_b, p_xn2);
    // 9. MLP up + GELU
    gemm_tc<<<dim3(FF_ / 128, ROWS / 128), 256, GEMM_SMEM>>>(
        p_xn2, pw_m1, mlp_b1, nullptr, p_h, ROWS, FF_, C_, 1);
    // 10. MLP down + residual(xmid) -> final output
    gemm_tc<<<dim3(C_ / 128, ROWS / 128), 256, GEMM_SMEM>>>(
        p_h, pw_m2, mlp_b2, p_xmid, out, ROWS, C_, FF_, 0);
}

// round 5
// speedup vs baseline: 3.3424x; 1.1885x over previous
#include <cuda_runtime.h>
#include <cuda_bf16.h>
#include <cstdint>
#include <math.h>

#define B_  2
#define L_  2048
#define C_  1024
#define H_  16
#define HD_ 64
#define FF_ 4096
#define ROWS (B_*L_)          // 4096
#define SCALE_ 0.125f         // 64^-0.5
#define EPS_ 1e-5f

// ---------------- scratch (allocation-free rule: __device__ globals) --------
__device__ float g_xn  [ROWS*C_];
__device__ float g_qkv [ROWS*3*C_];
__device__ float g_fbg [ROWS*C_];
__device__ float g_fb2 [ROWS*C_];
__device__ float g_Qe  [B_*H_*L_*128];   // [SCALE*q , fs*qb] (tf32)
__device__ float g_Ke  [B_*H_*L_*128];   // [k , kb] (tf32)
__device__ float g_V   [B_*H_*L_*HD_];   // (tf32)
__device__ float g_O   [ROWS*C_];
__device__ float g_xmid[ROWS*C_];
__device__ float g_xn2 [ROWS*C_];
__device__ float g_h   [ROWS*FF_];
// tf32-rounded weight copies
__device__ float g_w_qkv[C_*3*C_];
__device__ float g_w_fp2[C_*C_];
__device__ float g_w_out[C_*C_];
__device__ float g_w_m1 [C_*FF_];
__device__ float g_w_m2 [FF_*C_];

__device__ __forceinline__ float gelu_exact(float v) {
    return 0.5f * v * (1.0f + erff(v * 0.70710678118654752f));
}
__device__ __forceinline__ float to_tf32(float x) {
    unsigned int u;
    asm("cvt.rna.tf32.f32 %0, %1;" : "=r"(u) : "f"(x));
    return __uint_as_float(u);
}
__device__ __forceinline__ void cp16(float* smem_dst, const float* gmem_src) {
    unsigned int s = (unsigned int)__cvta_generic_to_shared(smem_dst);
    asm volatile("cp.async.cg.shared.global [%0], [%1], 16;" :: "r"(s), "l"(gmem_src));
}
#define MMA_TF32(c0,c1,c2,c3,a0,a1,a2,a3,b0,b1) \
    asm volatile("mma.sync.aligned.m16n8k8.row.col.f32.tf32.tf32.f32 " \
        "{%0,%1,%2,%3}, {%4,%5,%6,%7}, {%8,%9}, {%0,%1,%2,%3};" \
        : "+f"(c0), "+f"(c1), "+f"(c2), "+f"(c3) \
        : "r"(a0), "r"(a1), "r"(a2), "r"(a3), "r"(b0), "r"(b1))

// ---------------- tf32 rounding copy (weights pre-pass) ---------------------
__global__ void tf32_round_kernel(const float* __restrict__ X, float* __restrict__ Y, int n4) {
    int i = blockIdx.x * blockDim.x + threadIdx.x;
    if (i < n4) {
        float4 v = ((const float4*)X)[i];
        v.x = to_tf32(v.x); v.y = to_tf32(v.y);
        v.z = to_tf32(v.z); v.w = to_tf32(v.w);
        ((float4*)Y)[i] = v;
    }
}

// ---------------- LayerNorm (output tf32-rounded; feeds GEMM A) -------------
__global__ void ln_kernel(const float* __restrict__ X, const float* __restrict__ g,
                          const float* __restrict__ b, float* __restrict__ Y) {
    int row = blockIdx.x;
    int tid = threadIdx.x;
    const float4* xr = (const float4*)(X + (size_t)row * C_);
    float4 t = xr[tid];
    float s  = t.x + t.y + t.z + t.w;
    float sq = t.x*t.x + t.y*t.y + t.z*t.z + t.w*t.w;
    #pragma unroll
    for (int o = 16; o; o >>= 1) {
        s  += __shfl_xor_sync(0xffffffffu, s,  o);
        sq += __shfl_xor_sync(0xffffffffu, sq, o);
    }
    __shared__ float ws[8], wq[8];
    __shared__ float mean_s, rstd_s;
    int w = tid >> 5;
    if ((tid & 31) == 0) { ws[w] = s; wq[w] = sq; }
    __syncthreads();
    if (tid == 0) {
        float S = 0.f, Q = 0.f;
        #pragma unroll
        for (int i = 0; i < 8; i++) { S += ws[i]; Q += wq[i]; }
        float mean = S * (1.0f / C_);
        float var  = Q * (1.0f / C_) - mean * mean;
        mean_s = mean; rstd_s = rsqrtf(var + EPS_);
    }
    __syncthreads();
    float mean = mean_s, rstd = rstd_s;
    float4 gg = ((const float4*)g)[tid];
    float4 bb = ((const float4*)b)[tid];
    float4 o;
    o.x = to_tf32((t.x - mean) * rstd * gg.x + bb.x);
    o.y = to_tf32((t.y - mean) * rstd * gg.y + bb.y);
    o.z = to_tf32((t.z - mean) * rstd * gg.z + bb.z);
    o.w = to_tf32((t.w - mean) * rstd * gg.w + bb.w);
    ((float4*)(Y + (size_t)row * C_))[tid] = o;
}

// ------------- freq path stage 1: rank-1 outer + LN + exact GELU ------------
__global__ void fb1_kernel(const float* __restrict__ fd, const float* __restrict__ w1,
                           const float* __restrict__ b1, const float* __restrict__ g,
                           const float* __restrict__ bln, float* __restrict__ Y) {
    int row = blockIdx.x;
    int tid = threadIdx.x;
    float f = fd[row];
    float4 w = ((const float4*)w1)[tid];
    float4 bb = ((const float4*)b1)[tid];
    float4 t;
    t.x = f * w.x + bb.x; t.y = f * w.y + bb.y;
    t.z = f * w.z + bb.z; t.w = f * w.w + bb.w;
    float s  = t.x + t.y + t.z + t.w;
    float sq = t.x*t.x + t.y*t.y + t.z*t.z + t.w*t.w;
    #pragma unroll
    for (int o = 16; o; o >>= 1) {
        s  += __shfl_xor_sync(0xffffffffu, s,  o);
        sq += __shfl_xor_sync(0xffffffffu, sq, o);
    }
    __shared__ float ws[8], wqs[8];
    __shared__ float mean_s, rstd_s;
    int w5 = tid >> 5;
    if ((tid & 31) == 0) { ws[w5] = s; wqs[w5] = sq; }
    __syncthreads();
    if (tid == 0) {
        float S = 0.f, Q = 0.f;
        #pragma unroll
        for (int i = 0; i < 8; i++) { S += ws[i]; Q += wqs[i]; }
        float mean = S * (1.0f / C_);
        float var  = Q * (1.0f / C_) - mean * mean;
        mean_s = mean; rstd_s = rsqrtf(var + EPS_);
    }
    __syncthreads();
    float mean = mean_s, rstd = rstd_s;
    float4 gg = ((const float4*)g)[tid];
    float4 bl = ((const float4*)bln)[tid];
    float4 o;
    o.x = to_tf32(gelu_exact((t.x - mean) * rstd * gg.x + bl.x));
    o.y = to_tf32(gelu_exact((t.y - mean) * rstd * gg.y + bl.y));
    o.z = to_tf32(gelu_exact((t.z - mean) * rstd * gg.z + bl.z));
    o.w = to_tf32(gelu_exact((t.w - mean) * rstd * gg.w + bl.w));
    ((float4*)(Y + (size_t)row * C_))[tid] = o;
}

// ------- tf32 tensor-core GEMM v2: BK=32, 3-stage, occ 2, 1 barrier/iter ----
#define BK_ 32
#define ASTR 36        // A smem row stride (floats)
#define BSTR 136       // B smem row stride (floats)
#define A_ST (128*ASTR)          // 4608 floats
#define B_ST (BK_*BSTR)          // 4352 floats
#define STG  (A_ST + B_ST)       // 8960 floats = 35840 B
#define GEMM_SMEM (3*STG*4)      // 107520 B

__global__ __launch_bounds__(256, 2) void gemm_tc(
    const float* __restrict__ A, const float* __restrict__ Bm,
    const float* __restrict__ bias, const float* __restrict__ R,
    float* __restrict__ C, int M, int N, int K, int act) {
    extern __shared__ float sm[];
    int tid = threadIdx.x;
    int lane = tid & 31, wid = tid >> 5;
    int wm = wid & 3, wn = wid >> 2;       // 4 x 2 warp grid (32x64 per warp)
    int m0 = blockIdx.y * 128, n0 = blockIdx.x * 128;

    float c[2][8][4];
    #pragma unroll
    for (int mi = 0; mi < 2; mi++)
        #pragma unroll
        for (int ni = 0; ni < 8; ni++)
            #pragma unroll
            for (int q = 0; q < 4; q++) c[mi][ni][q] = 0.f;

    int NT = K / BK_;
    auto issue = [&](int t) {
        float* As = sm + (t % 3) * STG;
        float* Bs = As + A_ST;
        int k0 = t * BK_;
        #pragma unroll
        for (int it = 0; it < 4; it++) {
            int i = tid + it * 256;
            int am = i >> 3, akc = (i & 7) * 4;              // A: 128 x 32
            cp16(As + am * ASTR + akc, A + (size_t)(m0 + am) * K + k0 + akc);
            int bk = i >> 5, bn = (i & 31) * 4;              // B: 32 x 128
            cp16(Bs + bk * BSTR + bn, Bm + (size_t)(k0 + bk) * N + n0 + bn);
        }
        asm volatile("cp.async.commit_group;");
    };
    issue(0);
    issue(1);

    int r = lane >> 2, g = lane & 3;
    for (int t = 0; t < NT; t++) {
        if (t + 1 < NT) asm volatile("cp.async.wait_group 1;");
        else            asm volatile("cp.async.wait_group 0;");
        __syncthreads();   // tile t visible; all warps past compute(t-1)
        if (t + 2 < NT) issue(t + 2);

        const unsigned int* AsU = (const unsigned int*)(sm + (t % 3) * STG);
        const unsigned int* BsU = AsU + A_ST;
        #pragma unroll
        for (int ks = 0; ks < BK_; ks += 8) {
            unsigned int a[2][4], b[8][2];
            #pragma unroll
            for (int mi = 0; mi < 2; mi++) {
                int base = (wm * 32 + mi * 16 + r) * ASTR + ks + g;
                a[mi][0] = AsU[base];
                a[mi][1] = AsU[base + 8 * ASTR];
                a[mi][2] = AsU[base + 4];
                a[mi][3] = AsU[base + 8 * ASTR + 4];
            }
            #pragma unroll
            for (int ni = 0; ni < 8; ni++) {
                int nb = wn * 64 + ni * 8 + r;
                b[ni][0] = BsU[(ks + g) * BSTR + nb];
                b[ni][1] = BsU[(ks + g + 4) * BSTR + nb];
            }
            #pragma unroll
            for (int mi = 0; mi < 2; mi++)
                #pragma unroll
                for (int ni = 0; ni < 8; ni++)
                    MMA_TF32(c[mi][ni][0], c[mi][ni][1], c[mi][ni][2], c[mi][ni][3],
                             a[mi][0], a[mi][1], a[mi][2], a[mi][3],
                             b[ni][0], b[ni][1]);
        }
        // no trailing barrier: next iteration's barrier orders buffer reuse
    }

    #pragma unroll
    for (int mi = 0; mi < 2; mi++) {
        int row0 = m0 + wm * 32 + mi * 16 + r;
        #pragma unroll
        for (int ni = 0; ni < 8; ni++) {
            int col = n0 + wn * 64 + ni * 8 + g * 2;
            float b0 = bias[col], b1 = bias[col + 1];
            #pragma unroll
            for (int half = 0; half < 2; half++) {
                int row = row0 + half * 8;
                float v0 = c[mi][ni][half * 2 + 0] + b0;
                float v1 = c[mi][ni][half * 2 + 1] + b1;
                if (act == 1) { v0 = to_tf32(gelu_exact(v0)); v1 = to_tf32(gelu_exact(v1)); }
                if (R) {
                    v0 += R[(size_t)row * N + col];
                    v1 += R[(size_t)row * N + col + 1];
                }
                *(float2*)(C + (size_t)row * N + col) = make_float2(v0, v1);
            }
        }
    }
}

// ------- build extended Q/K and V (tf32-rounded outputs for mma attn) -------
__global__ void build_ext_kernel(const float* __restrict__ qkv, const float* __restrict__ fb2,
                                 const float* __restrict__ wqw, const float* __restrict__ wqb,
                                 const float* __restrict__ wkw, const float* __restrict__ wkb,
                                 const float* __restrict__ fscale,
                                 float* __restrict__ Qe, float* __restrict__ Ke,
                                 float* __restrict__ Vo) {
    __shared__ float swq[64 * 64], swk[64 * 64], sfb[64 * 65];
    int bh = blockIdx.y;
    int lt = blockIdx.x;
    int b = bh >> 4, h = bh & 15;
    int l0 = lt * 64;
    int tid = threadIdx.x;
    for (int i = tid; i < 4096; i += 256) { swq[i] = wqw[i]; swk[i] = wkw[i]; }
    for (int i = tid; i < 4096; i += 256) {
        int r = i >> 6, c = i & 63;
        sfb[r * 65 + c] = fb2[(size_t)(b * L_ + l0 + r) * C_ + h * 64 + c];
    }
    __syncthreads();
    int r = tid >> 2, q4 = tid & 3;
    float fs = fscale[0];
    float aq[16], ak[16];
    #pragma unroll
    for (int d = 0; d < 16; d++) { aq[d] = wqb[q4 * 16 + d]; ak[d] = wkb[q4 * 16 + d]; }
    for (int e = 0; e < 64; e++) {
        float fe = sfb[r * 65 + e];
        #pragma unroll
        for (int d = 0; d < 16; d++) {
            aq[d] += fe * swq[e * 64 + q4 * 16 + d];
            ak[d] += fe * swk[e * 64 + q4 * 16 + d];
        }
    }
    size_t base = (size_t)bh * L_ + l0 + r;
    float* qrow = Qe + base * 128;
    float* krow = Ke + base * 128;
    size_t qkvrow = (size_t)(b * L_ + l0 + r) * (3 * C_);
    #pragma unroll
    for (int dd = 0; dd < 16; dd++) {
        int d = q4 * 16 + dd;
        qrow[64 + d] = to_tf32(fs * aq[dd]);
        krow[64 + d] = to_tf32(ak[dd]);
        qrow[d] = to_tf32(SCALE_ * qkv[qkvrow + h * 64 + d]);
        krow[d] = to_tf32(qkv[qkvrow + C_ + h * 64 + d]);
        Vo[base * 64 + d] = to_tf32(qkv[qkvrow + 2 * C_ + h * 64 + d]);
    }
}

// ------------- tensor-core flash attention, D_qk=128, D_v=64 ----------------
#define QSTR 132
#define KSTR 132
#define VSTR 68
#define PSTR 68
#define ATTN_SM_FLOATS (128*QSTR + 2*64*KSTR + 2*64*VSTR)   // 42496 floats
__global__ __launch_bounds__(256, 1) void attn_tc(
    const float* __restrict__ Qe, const float* __restrict__ Ke,
    const float* __restrict__ V, float* __restrict__ O) {
    extern __shared__ float sm[];
    float* Qs  = sm;                       // 128 x 132; reused as Ps (128 x 68)
    float* Ks0 = sm + 128 * QSTR;          // 2 x 64 x 132
    float* Vs0 = Ks0 + 2 * 64 * KSTR;      // 2 x 64 x 68
    int qt = blockIdx.x, bh = blockIdx.y;
    int tid = threadIdx.x, lane = tid & 31, wid = tid >> 5;
    int r = lane >> 2, g = lane & 3;
    const float* Qp = Qe + ((size_t)bh * L_ + qt * 128) * 128;
    const float* Kp = Ke + (size_t)bh * L_ * 128;
    const float* Vp = V + (size_t)bh * L_ * 64;

    auto issueKV = [&](int t) {
        float* Ks = Ks0 + (t & 1) * 64 * KSTR;
        float* Vs = Vs0 + (t & 1) * 64 * VSTR;
        const float* Kt = Kp + (size_t)t * 64 * 128;
        const float* Vt = Vp + (size_t)t * 64 * 64;
        #pragma unroll
        for (int it = 0; it < 8; it++) {
            int i = tid + it * 256;
            int rr = i >> 5, cc = (i & 31) * 4;
            cp16(Ks + rr * KSTR + cc, Kt + rr * 128 + cc);
        }
        #pragma unroll
        for (int it = 0; it < 4; it++) {
            int i = tid + it * 256;
            int rr = i >> 4, cc = (i & 15) * 4;
            cp16(Vs + rr * VSTR + cc, Vt + rr * 64 + cc);
        }
        asm volatile("cp.async.commit_group;");
    };
    issueKV(0);

    for (int i = tid; i < 4096; i += 256) {
        int rr = i >> 5, cc = (i & 31) * 4;
        *(float4*)(Qs + rr * QSTR + cc) = *(const float4*)(Qp + rr * 128 + cc);
    }
    __syncthreads();
    unsigned int qf[16][4];
    const unsigned int* QsU = (const unsigned int*)Qs;
    #pragma unroll
    for (int ks = 0; ks < 16; ks++) {
        int base = (wid * 16 + r) * QSTR + ks * 8 + g;
        qf[ks][0] = QsU[base];
        qf[ks][1] = QsU[base + 8 * QSTR];
        qf[ks][2] = QsU[base + 4];
        qf[ks][3] = QsU[base + 8 * QSTR + 4];
    }
    __syncthreads();
    float* Ps = Qs;
    unsigned int* PsU = (unsigned int*)Ps;

    float o[8][4];
    #pragma unroll
    for (int ni = 0; ni < 8; ni++)
        #pragma unroll
        for (int q = 0; q < 4; q++) o[ni][q] = 0.f;
    float m0 = -1e30f, m1 = -1e30f, l0 = 0.f, l1 = 0.f;

    for (int t = 0; t < L_ / 64; t++) {
        if (t + 1 < L_ / 64) {
            issueKV(t + 1);
            asm volatile("cp.async.wait_group 1;");
        } else {
            asm volatile("cp.async.wait_group 0;");
        }
        __syncthreads();
        const unsigned int* KsU = (const unsigned int*)(Ks0 + (t & 1) * 64 * KSTR);
        const unsigned int* VsU = (const unsigned int*)(Vs0 + (t & 1) * 64 * VSTR);

        float c[8][4];
        #pragma unroll
        for (int ni = 0; ni < 8; ni++)
            #pragma unroll
            for (int q = 0; q < 4; q++) c[ni][q] = 0.f;
        #pragma unroll
        for (int ks = 0; ks < 16; ks++) {
            unsigned int b[8][2];
            #pragma unroll
            for (int ni = 0; ni < 8; ni++) {
                int nb = ni * 8 + r;
                b[ni][0] = KsU[nb * KSTR + ks * 8 + g];
                b[ni][1] = KsU[nb * KSTR + ks * 8 + g + 4];
            }
            #pragma unroll
            for (int ni = 0; ni < 8; ni++)
                MMA_TF32(c[ni][0], c[ni][1], c[ni][2], c[ni][3],
                         qf[ks][0], qf[ks][1], qf[ks][2], qf[ks][3],
                         b[ni][0], b[ni][1]);
        }

        float mx0 = -1e30f, mx1 = -1e30f;
        #pragma unroll
        for (int ni = 0; ni < 8; ni++) {
            mx0 = fmaxf(mx0, fmaxf(c[ni][0], c[ni][1]));
            mx1 = fmaxf(mx1, fmaxf(c[ni][2], c[ni][3]));
        }
        #pragma unroll
        for (int ofs = 1; ofs <= 2; ofs <<= 1) {
            mx0 = fmaxf(mx0, __shfl_xor_sync(0xffffffffu, mx0, ofs));
            mx1 = fmaxf(mx1, __shfl_xor_sync(0xffffffffu, mx1, ofs));
        }
        float mn0 = fmaxf(m0, mx0), mn1 = fmaxf(m1, mx1);
        float al0 = __expf(m0 - mn0), al1 = __expf(m1 - mn1);
        float rs0 = 0.f, rs1 = 0.f;
        int prow0 = (wid * 16 + r) * PSTR + 2 * g;
        int prow1 = prow0 + 8 * PSTR;
        #pragma unroll
        for (int ni = 0; ni < 8; ni++) {
            float p0 = __expf(c[ni][0] - mn0);
            float p1 = __expf(c[ni][1] - mn0);
            float p2 = __expf(c[ni][2] - mn1);
            float p3 = __expf(c[ni][3] - mn1);
            rs0 += p0 + p1; rs1 += p2 + p3;
            *(float2*)(Ps + prow0 + ni * 8) = make_float2(to_tf32(p0), to_tf32(p1));
            *(float2*)(Ps + prow1 + ni * 8) = make_float2(to_tf32(p2), to_tf32(p3));
        }
        #pragma unroll
        for (int ofs = 1; ofs <= 2; ofs <<= 1) {
            rs0 += __shfl_xor_sync(0xffffffffu, rs0, ofs);
            rs1 += __shfl_xor_sync(0xffffffffu, rs1, ofs);
        }
        l0 = l0 * al0 + rs0; l1 = l1 * al1 + rs1;
        m0 = mn0; m1 = mn1;
        #pragma unroll
        for (int ni = 0; ni < 8; ni++) {
            o[ni][0] *= al0; o[ni][1] *= al0;
            o[ni][2] *= al1; o[ni][3] *= al1;
        }
        __syncwarp();

        #pragma unroll
        for (int ks = 0; ks < 8; ks++) {
            unsigned int a[4], b[8][2];
            int abase = (wid * 16 + r) * PSTR + ks * 8 + g;
            a[0] = PsU[abase];
            a[1] = PsU[abase + 8 * PSTR];
            a[2] = PsU[abase + 4];
            a[3] = PsU[abase + 8 * PSTR + 4];
            #pragma unroll
            for (int ni = 0; ni < 8; ni++) {
                b[ni][0] = VsU[(ks * 8 + g) * VSTR + ni * 8 + r];
                b[ni][1] = VsU[(ks * 8 + g + 4) * VSTR + ni * 8 + r];
            }
            #pragma unroll
            for (int ni = 0; ni < 8; ni++)
                MMA_TF32(o[ni][0], o[ni][1], o[ni][2], o[ni][3],
                         a[0], a[1], a[2], a[3], b[ni][0], b[ni][1]);
        }
        __syncthreads();
    }

    int b = bh >> 4, h = bh & 15;
    int l0row = qt * 128 + wid * 16 + r;
    float inv0 = 1.0f / l0, inv1 = 1.0f / l1;
    #pragma unroll
    for (int ni = 0; ni < 8; ni++) {
        int col = h * 64 + ni * 8 + 2 * g;
        *(float2*)(O + (size_t)(b * L_ + l0row) * C_ + col) =
            make_float2(to_tf32(o[ni][0] * inv0), to_tf32(o[ni][1] * inv0));
        *(float2*)(O + (size_t)(b * L_ + l0row + 8) * C_ + col) =
            make_float2(to_tf32(o[ni][2] * inv1), to_tf32(o[ni][3] * inv1));
    }
}

// ---------------------------------------------------------------------------
extern "C" void kernel_launch(void* const* d_in, const int* in_sizes, int n_in,
                              void* d_out, int out_size) {
    const float* x        = (const float*)d_in[0];
    const float* freqd    = (const float*)d_in[1];
    const float* qkv_w    = (const float*)d_in[2];
    const float* qkv_b    = (const float*)d_in[3];
    const float* fp_w1    = (const float*)d_in[4];
    const float* fp_b1    = (const float*)d_in[5];
    const float* fp_ln_g  = (const float*)d_in[6];
    const float* fp_ln_b  = (const float*)d_in[7];
    const float* fp_w2    = (const float*)d_in[8];
    const float* fp_b2    = (const float*)d_in[9];
    const float* wq_w     = (const float*)d_in[10];
    const float* wq_b     = (const float*)d_in[11];
    const float* wk_w     = (const float*)d_in[12];
    const float* wk_b     = (const float*)d_in[13];
    const float* out_w    = (const float*)d_in[14];
    const float* out_b    = (const float*)d_in[15];
    const float* n1_g     = (const float*)d_in[16];
    const float* n1_b     = (const float*)d_in[17];
    const float* n2_g     = (const float*)d_in[18];
    const float* n2_b     = (const float*)d_in[19];
    const float* mlp_w1   = (const float*)d_in[20];
    const float* mlp_b1   = (const float*)d_in[21];
    const float* mlp_w2   = (const float*)d_in[22];
    const float* mlp_b2   = (const float*)d_in[23];
    const float* fscale   = (const float*)d_in[24];
    float* out = (float*)d_out;

    float *p_xn, *p_qkv, *p_fbg, *p_fb2, *p_Qe, *p_Ke, *p_V, *p_O, *p_xmid, *p_xn2, *p_h;
    float *pw_qkv, *pw_fp2, *pw_out, *pw_m1, *pw_m2;
    cudaGetSymbolAddress((void**)&p_xn,   g_xn);
    cudaGetSymbolAddress((void**)&p_qkv,  g_qkv);
    cudaGetSymbolAddress((void**)&p_fbg,  g_fbg);
    cudaGetSymbolAddress((void**)&p_fb2,  g_fb2);
    cudaGetSymbolAddress((void**)&p_Qe,   g_Qe);
    cudaGetSymbolAddress((void**)&p_Ke,   g_Ke);
    cudaGetSymbolAddress((void**)&p_V,    g_V);
    cudaGetSymbolAddress((void**)&p_O,    g_O);
    cudaGetSymbolAddress((void**)&p_xmid, g_xmid);
    cudaGetSymbolAddress((void**)&p_xn2,  g_xn2);
    cudaGetSymbolAddress((void**)&p_h,    g_h);
    cudaGetSymbolAddress((void**)&pw_qkv, g_w_qkv);
    cudaGetSymbolAddress((void**)&pw_fp2, g_w_fp2);
    cudaGetSymbolAddress((void**)&pw_out, g_w_out);
    cudaGetSymbolAddress((void**)&pw_m1,  g_w_m1);
    cudaGetSymbolAddress((void**)&pw_m2,  g_w_m2);

    cudaFuncSetAttribute(gemm_tc, cudaFuncAttributeMaxDynamicSharedMemorySize, GEMM_SMEM);
    cudaFuncSetAttribute(attn_tc, cudaFuncAttributeMaxDynamicSharedMemorySize,
                         ATTN_SM_FLOATS * (int)sizeof(float));

    // 0. weight tf32 pre-rounding
    tf32_round_kernel<<<(3*C_*C_/4 + 255)/256, 256>>>(qkv_w,  pw_qkv, 3*C_*C_/4);
    tf32_round_kernel<<<(C_*C_/4   + 255)/256, 256>>>(fp_w2,  pw_fp2, C_*C_/4);
    tf32_round_kernel<<<(C_*C_/4   + 255)/256, 256>>>(out_w,  pw_out, C_*C_/4);
    tf32_round_kernel<<<(C_*FF_/4  + 255)/256, 256>>>(mlp_w1, pw_m1,  C_*FF_/4);
    tf32_round_kernel<<<(FF_*C_/4  + 255)/256, 256>>>(mlp_w2, pw_m2,  FF_*C_/4);

    // 1. LN1
    ln_kernel<<<ROWS, 256>>>(x, n1_g, n1_b, p_xn);
    // 2. QKV projection
    gemm_tc<<<dim3(3 * C_ / 128, ROWS / 128), 256, GEMM_SMEM>>>(
        p_xn, pw_qkv, qkv_b, nullptr, p_qkv, ROWS, 3 * C_, C_, 0);
    // 3. freq rank-1 + LN + GELU
    fb1_kernel<<<ROWS, 256>>>(freqd, fp_w1, fp_b1, fp_ln_g, fp_ln_b, p_fbg);
    // 4. fb @ fp_w2
    gemm_tc<<<dim3(C_ / 128, ROWS / 128), 256, GEMM_SMEM>>>(
        p_fbg, pw_fp2, fp_b2, nullptr, p_fb2, ROWS, C_, C_, 0);
    // 5. build extended Q/K and V (tf32)
    build_ext_kernel<<<dim3(L_ / 64, B_ * H_), 256>>>(p_qkv, p_fb2, wq_w, wq_b,
                                                      wk_w, wk_b, fscale,
                                                      p_Qe, p_Ke, p_V);
    // 6. tensor-core flash attention
    attn_tc<<<dim3(L_ / 128, B_ * H_), 256,
              ATTN_SM_FLOATS * sizeof(float)>>>(p_Qe, p_Ke, p_V, p_O);
    // 7. out projection + residual(x)
    gemm_tc<<<dim3(C_ / 128, ROWS / 128), 256, GEMM_SMEM>>>(
        p_O, pw_out, out_b, x, p_xmid, ROWS, C_, C_, 0);
    // 8. LN2
    ln_kernel<<<ROWS, 256>>>(p_xmid, n2_g, n2_b, p_xn2);
    // 9. MLP up + GELU
    gemm_tc<<<dim3(FF_ / 128, ROWS / 128), 256, GEMM_SMEM>>>(
        p_xn2, pw_m1, mlp_b1, nullptr, p_h, ROWS, FF_, C_, 1);
    // 10. MLP down + residual(xmid) -> final output
    gemm_tc<<<dim3(C_ / 128, ROWS / 128), 256, GEMM_SMEM>>>(
        p_h, pw_m2, mlp_b2, p_xmid, out, ROWS, C_, FF_, 0);
}